// round 1
// baseline (speedup 1.0000x reference)
#include <cuda_runtime.h>
#include <math.h>

// Problem dims (fixed)
#define Bz 4
#define Tt 2048
#define Cc 1024
#define Hh 16
#define DHd 64
#define MM (Bz*Tt)      // 8192 rows
#define FFd (4*Cc)      // 4096

// ---------------- scratch (static device allocations are allowed) ----------
__device__ float g_h[(size_t)MM * Cc];     // LN output (reused for LN2)
__device__ float g_q[(size_t)MM * Cc];     // [B,H,T,DH]
__device__ float g_k[(size_t)MM * Cc];
__device__ float g_v[(size_t)MM * Cc];
__device__ float g_attn[(size_t)MM * Cc];  // [B,T,C]
__device__ float g_ff[(size_t)MM * FFd];   // MLP hidden

// ---------------- LayerNorm: one block per row, 256 threads, 4 elems/thread
__global__ void __launch_bounds__(256) ln_kernel(
    const float* __restrict__ x, const float* __restrict__ g,
    const float* __restrict__ be, float* __restrict__ out)
{
    int row = blockIdx.x;
    int t = threadIdx.x;
    const float4* xr = reinterpret_cast<const float4*>(x + (size_t)row * Cc);
    float4 xv = xr[t];
    float s  = xv.x + xv.y + xv.z + xv.w;
    float s2 = xv.x*xv.x + xv.y*xv.y + xv.z*xv.z + xv.w*xv.w;
    #pragma unroll
    for (int off = 16; off > 0; off >>= 1) {
        s  += __shfl_xor_sync(0xffffffffu, s,  off);
        s2 += __shfl_xor_sync(0xffffffffu, s2, off);
    }
    __shared__ float ss[8], ss2[8];
    int w = t >> 5, lane = t & 31;
    if (lane == 0) { ss[w] = s; ss2[w] = s2; }
    __syncthreads();
    if (w == 0) {
        s  = (lane < 8) ? ss[lane]  : 0.f;
        s2 = (lane < 8) ? ss2[lane] : 0.f;
        #pragma unroll
        for (int off = 4; off > 0; off >>= 1) {
            s  += __shfl_xor_sync(0xffffffffu, s,  off);
            s2 += __shfl_xor_sync(0xffffffffu, s2, off);
        }
        if (lane == 0) { ss[0] = s; ss2[0] = s2; }
    }
    __syncthreads();
    float mu  = ss[0] * (1.f / Cc);
    float var = ss2[0] * (1.f / Cc) - mu * mu;
    float inv = rsqrtf(var + 1e-5f);
    float4 gv = reinterpret_cast<const float4*>(g)[t];
    float4 bv = reinterpret_cast<const float4*>(be)[t];
    float4 o;
    o.x = (xv.x - mu) * inv * gv.x + bv.x;
    o.y = (xv.y - mu) * inv * gv.y + bv.y;
    o.z = (xv.z - mu) * inv * gv.z + bv.z;
    o.w = (xv.w - mu) * inv * gv.w + bv.w;
    reinterpret_cast<float4*>(out + (size_t)row * Cc)[t] = o;
}

// ---------------- SGEMM 128x128x8, 8x8 microtile, 256 threads ----------------
// C[m,n] = sum_k A[m,k]*B[k,n], all row-major, dims divisible by tile sizes.
// Epilogue modes:
#define EPI_QKV   0   // scatter to [B,H,T,DH]
#define EPI_RESID 1   // out = acc + bias[n] + res[m,n]
#define EPI_RELU  2   // out = relu(acc + bias[n])

template<int MODE>
__global__ void __launch_bounds__(256) sgemm_kernel(
    int M, int N, int K,
    const float* __restrict__ A, const float* __restrict__ Bm,
    const float* __restrict__ bias, const float* __restrict__ res,
    float* __restrict__ Cout)
{
    __shared__ float As[8][128];
    __shared__ float Bs[8][128];
    int tid = threadIdx.x;
    int m0 = blockIdx.y * 128, n0 = blockIdx.x * 128;
    int tx = tid & 15, ty = tid >> 4;

    int aRow = tid >> 1;            // 0..127
    int aCol = (tid & 1) * 4;       // 0 or 4
    int bRow = tid >> 5;            // 0..7
    int bCol = (tid & 31) * 4;      // 0..124

    const float* Aptr = A + (size_t)(m0 + aRow) * K + aCol;
    const float* Bptr = Bm + (size_t)bRow * N + n0 + bCol;

    float acc[8][8];
    #pragma unroll
    for (int i = 0; i < 8; i++)
        #pragma unroll
        for (int j = 0; j < 8; j++) acc[i][j] = 0.f;

    for (int k0 = 0; k0 < K; k0 += 8) {
        float4 av = *reinterpret_cast<const float4*>(Aptr + k0);
        float4 bv = *reinterpret_cast<const float4*>(Bptr + (size_t)k0 * N);
        As[aCol + 0][aRow] = av.x;
        As[aCol + 1][aRow] = av.y;
        As[aCol + 2][aRow] = av.z;
        As[aCol + 3][aRow] = av.w;
        *reinterpret_cast<float4*>(&Bs[bRow][bCol]) = bv;
        __syncthreads();
        #pragma unroll
        for (int kk = 0; kk < 8; kk++) {
            float ar[8], br[8];
            #pragma unroll
            for (int i = 0; i < 8; i++) ar[i] = As[kk][ty * 8 + i];
            #pragma unroll
            for (int j = 0; j < 8; j++) br[j] = Bs[kk][tx * 8 + j];
            #pragma unroll
            for (int i = 0; i < 8; i++)
                #pragma unroll
                for (int j = 0; j < 8; j++)
                    acc[i][j] += ar[i] * br[j];
        }
        __syncthreads();
    }

    #pragma unroll
    for (int i = 0; i < 8; i++) {
        int m = m0 + ty * 8 + i;
        #pragma unroll
        for (int j = 0; j < 8; j++) {
            int n = n0 + tx * 8 + j;
            float vacc = acc[i][j];
            if (MODE == EPI_QKV) {
                int b = m / Tt, t = m % Tt;
                int hh = n / DHd, d = n % DHd;
                Cout[(((size_t)(b * Hh + hh) * Tt) + t) * DHd + d] = vacc;
            } else if (MODE == EPI_RESID) {
                size_t idx = (size_t)m * N + n;
                Cout[idx] = vacc + bias[n] + res[idx];
            } else { // EPI_RELU
                size_t idx = (size_t)m * N + n;
                Cout[idx] = fmaxf(vacc + bias[n], 0.f);
            }
        }
    }
}

// ---------------- Flash attention, fp32, causal ----------------
// Grid: (T/64, H, B). 256 threads. Each block: 64 query rows.
// Thread t: row r = t/4, column/outdim group cg = t%4 (16 cols each).
__global__ void __launch_bounds__(256) attn_kernel(
    const float* __restrict__ q, const float* __restrict__ k,
    const float* __restrict__ v, float* __restrict__ out)
{
    extern __shared__ float sm[];
    const int LD = 65;
    float* Qs = sm;
    float* Ks = Qs + 64 * LD;
    float* Vs = Ks + 64 * LD;
    float* Ps = Vs + 64 * LD;

    int qt = blockIdx.x, h = blockIdx.y, b = blockIdx.z;
    int tid = threadIdx.x;
    int r = tid >> 2, cg = tid & 3;
    int qglob = qt * 64 + r;

    size_t bh_row0 = (size_t)(b * Hh + h) * Tt;

    // Load Q tile [64 x 64]
    #pragma unroll
    for (int rep = 0; rep < 4; rep++) {
        int idx = rep * 256 + tid;
        int lr = idx >> 4;
        int lc = (idx & 15) * 4;
        float4 qv = *reinterpret_cast<const float4*>(
            q + (bh_row0 + (size_t)qt * 64 + lr) * DHd + lc);
        Qs[lr * LD + lc + 0] = qv.x;
        Qs[lr * LD + lc + 1] = qv.y;
        Qs[lr * LD + lc + 2] = qv.z;
        Qs[lr * LD + lc + 3] = qv.w;
    }

    float m_i = -INFINITY, l_i = 0.f;
    float o[16];
    #pragma unroll
    for (int jj = 0; jj < 16; jj++) o[jj] = 0.f;

    const float scale = 0.125f; // 1/sqrt(64)

    for (int j = 0; j <= qt; j++) {
        __syncthreads();   // prior iteration's K/V reads done
        // Load K,V tiles [64 x 64] each
        #pragma unroll
        for (int rep = 0; rep < 4; rep++) {
            int idx = rep * 256 + tid;
            int lr = idx >> 4;
            int lc = (idx & 15) * 4;
            size_t grow = (bh_row0 + (size_t)j * 64 + lr) * DHd + lc;
            float4 kv = *reinterpret_cast<const float4*>(k + grow);
            float4 vv = *reinterpret_cast<const float4*>(v + grow);
            Ks[lr * LD + lc + 0] = kv.x;
            Ks[lr * LD + lc + 1] = kv.y;
            Ks[lr * LD + lc + 2] = kv.z;
            Ks[lr * LD + lc + 3] = kv.w;
            Vs[lr * LD + lc + 0] = vv.x;
            Vs[lr * LD + lc + 1] = vv.y;
            Vs[lr * LD + lc + 2] = vv.z;
            Vs[lr * LD + lc + 3] = vv.w;
        }
        __syncthreads();

        // S = Q K^T for 16 columns of this row
        float svals[16];
        #pragma unroll
        for (int jj = 0; jj < 16; jj++) svals[jj] = 0.f;
        #pragma unroll 4
        for (int d = 0; d < 64; d++) {
            float qv = Qs[r * LD + d];
            #pragma unroll
            for (int jj = 0; jj < 16; jj++)
                svals[jj] += qv * Ks[(cg * 16 + jj) * LD + d];
        }

        // mask + scale + tile max
        int kbase = j * 64;
        float tmax = -INFINITY;
        #pragma unroll
        for (int jj = 0; jj < 16; jj++) {
            int c = cg * 16 + jj;
            if (kbase + c > qglob) svals[jj] = -INFINITY;
            else                   svals[jj] *= scale;
            tmax = fmaxf(tmax, svals[jj]);
        }
        tmax = fmaxf(tmax, __shfl_xor_sync(0xffffffffu, tmax, 1));
        tmax = fmaxf(tmax, __shfl_xor_sync(0xffffffffu, tmax, 2));

        float m_new = fmaxf(m_i, tmax);
        float alpha = __expf(m_i - m_new);
        float psum = 0.f;
        #pragma unroll
        for (int jj = 0; jj < 16; jj++) {
            float p = __expf(svals[jj] - m_new);
            psum += p;
            Ps[r * LD + cg * 16 + jj] = p;
        }
        psum += __shfl_xor_sync(0xffffffffu, psum, 1);
        psum += __shfl_xor_sync(0xffffffffu, psum, 2);
        l_i = l_i * alpha + psum;
        m_i = m_new;
        __syncwarp();   // Ps row visibility within the 4-thread row group

        #pragma unroll
        for (int jj = 0; jj < 16; jj++) o[jj] *= alpha;
        #pragma unroll 4
        for (int s = 0; s < 64; s++) {
            float p = Ps[r * LD + s];
            #pragma unroll
            for (int jj = 0; jj < 16; jj++)
                o[jj] += p * Vs[s * LD + cg * 16 + jj];
        }
    }

    // Write output in [B,T,C] layout (head-concat)
    float invl = 1.f / l_i;
    size_t obase = ((size_t)b * Tt + qglob) * Cc + h * DHd + cg * 16;
    #pragma unroll
    for (int jj4 = 0; jj4 < 4; jj4++) {
        float4 ov;
        ov.x = o[jj4 * 4 + 0] * invl;
        ov.y = o[jj4 * 4 + 1] * invl;
        ov.z = o[jj4 * 4 + 2] * invl;
        ov.w = o[jj4 * 4 + 3] * invl;
        *reinterpret_cast<float4*>(out + obase + jj4 * 4) = ov;
    }
}

// ---------------- launch ----------------
extern "C" void kernel_launch(void* const* d_in, const int* in_sizes, int n_in,
                              void* d_out, int out_size)
{
    const float* x   = (const float*)d_in[0];
    const float* Wq  = (const float*)d_in[1];
    const float* Wk  = (const float*)d_in[2];
    const float* Wv  = (const float*)d_in[3];
    const float* Wp  = (const float*)d_in[4];
    const float* bp  = (const float*)d_in[5];
    const float* W1  = (const float*)d_in[6];
    const float* b1  = (const float*)d_in[7];
    const float* W2  = (const float*)d_in[8];
    const float* b2  = (const float*)d_in[9];
    const float* g1  = (const float*)d_in[10];
    const float* be1 = (const float*)d_in[11];
    const float* g2  = (const float*)d_in[12];
    const float* be2 = (const float*)d_in[13];
    float* out = (float*)d_out;

    float *h, *q, *k, *v, *attn, *ff;
    cudaGetSymbolAddress((void**)&h,    g_h);
    cudaGetSymbolAddress((void**)&q,    g_q);
    cudaGetSymbolAddress((void**)&k,    g_k);
    cudaGetSymbolAddress((void**)&v,    g_v);
    cudaGetSymbolAddress((void**)&attn, g_attn);
    cudaGetSymbolAddress((void**)&ff,   g_ff);

    const int smem_attn = 4 * 64 * 65 * sizeof(float); // 66560 B
    cudaFuncSetAttribute(attn_kernel,
                         cudaFuncAttributeMaxDynamicSharedMemorySize, smem_attn);

    dim3 g_c(Cc / 128, MM / 128);     // (8, 64)
    dim3 g_ff4(FFd / 128, MM / 128);  // (32, 64)

    // 1. LN1
    ln_kernel<<<MM, 256>>>(x, g1, be1, h);
    // 2. Q,K,V projections (scatter to [B,H,T,DH])
    sgemm_kernel<EPI_QKV><<<g_c, 256>>>(MM, Cc, Cc, h, Wq, nullptr, nullptr, q);
    sgemm_kernel<EPI_QKV><<<g_c, 256>>>(MM, Cc, Cc, h, Wk, nullptr, nullptr, k);
    sgemm_kernel<EPI_QKV><<<g_c, 256>>>(MM, Cc, Cc, h, Wv, nullptr, nullptr, v);
    // 3. Causal flash attention -> [B,T,C]
    attn_kernel<<<dim3(Tt / 64, Hh, Bz), 256, smem_attn>>>(q, k, v, attn);
    // 4. Output projection + bias + residual -> d_out
    sgemm_kernel<EPI_RESID><<<g_c, 256>>>(MM, Cc, Cc, attn, Wp, bp, x, out);
    // 5. LN2
    ln_kernel<<<MM, 256>>>(out, g2, be2, h);
    // 6. MLP up + ReLU
    sgemm_kernel<EPI_RELU><<<g_ff4, 256>>>(MM, FFd, Cc, h, W1, b1, nullptr, ff);
    // 7. MLP down + bias + residual (in-place residual read is same-thread safe)
    sgemm_kernel<EPI_RESID><<<g_c, 256>>>(MM, Cc, FFd, ff, W2, b2, out, out);
}

// round 3
// speedup vs baseline: 1.5104x; 1.5104x over previous
#include <cuda_runtime.h>
#include <cuda_bf16.h>
#include <math.h>
#include <stdint.h>

// Problem dims (fixed)
#define Bz 4
#define Tt 2048
#define Cc 1024
#define Hh 16
#define DHd 64
#define MM (Bz*Tt)      // 8192
#define FFd (4*Cc)      // 4096

typedef __nv_bfloat16 bf16;

// ---------------- scratch ----------------
__device__ bf16  g_h_hi[(size_t)MM * Cc];
__device__ bf16  g_h_lo[(size_t)MM * Cc];
__device__ float g_q[(size_t)MM * Cc];     // [B,H,T,DH]
__device__ float g_k[(size_t)MM * Cc];
__device__ float g_v[(size_t)MM * Cc];
__device__ bf16  g_attn_hi[(size_t)MM * Cc];
__device__ bf16  g_attn_lo[(size_t)MM * Cc];
__device__ bf16  g_ff_hi[(size_t)MM * FFd];
__device__ bf16  g_ff_lo[(size_t)MM * FFd];
// transposed + split weights [N, K]
__device__ bf16 g_WqT_hi[(size_t)Cc * Cc],  g_WqT_lo[(size_t)Cc * Cc];
__device__ bf16 g_WkT_hi[(size_t)Cc * Cc],  g_WkT_lo[(size_t)Cc * Cc];
__device__ bf16 g_WvT_hi[(size_t)Cc * Cc],  g_WvT_lo[(size_t)Cc * Cc];
__device__ bf16 g_WpT_hi[(size_t)Cc * Cc],  g_WpT_lo[(size_t)Cc * Cc];
__device__ bf16 g_W1T_hi[(size_t)FFd * Cc], g_W1T_lo[(size_t)FFd * Cc];
__device__ bf16 g_W2T_hi[(size_t)Cc * FFd], g_W2T_lo[(size_t)Cc * FFd];

// ---------------- helpers ----------------
__device__ __forceinline__ uint32_t smem_u32(const void* p) {
    uint32_t a;
    asm("{ .reg .u64 t; cvta.to.shared.u64 t, %1; cvt.u32.u64 %0, t; }"
        : "=r"(a) : "l"(p));
    return a;
}
__device__ __forceinline__ void cpasync16(uint32_t s, const void* g) {
    asm volatile("cp.async.cg.shared.global [%0], [%1], 16;" :: "r"(s), "l"(g));
}
__device__ __forceinline__ void cp_commit() {
    asm volatile("cp.async.commit_group;" ::: "memory");
}
__device__ __forceinline__ void ldsm4(uint32_t& r0, uint32_t& r1, uint32_t& r2,
                                      uint32_t& r3, uint32_t a) {
    asm volatile("ldmatrix.sync.aligned.m8n8.x4.shared.b16 {%0,%1,%2,%3}, [%4];"
                 : "=r"(r0), "=r"(r1), "=r"(r2), "=r"(r3) : "r"(a));
}
__device__ __forceinline__ void mma16816(float* c, const uint32_t* a,
                                         uint32_t b0, uint32_t b1) {
    asm volatile(
        "mma.sync.aligned.m16n8k16.row.col.f32.bf16.bf16.f32 "
        "{%0,%1,%2,%3}, {%4,%5,%6,%7}, {%8,%9}, {%0,%1,%2,%3};"
        : "+f"(c[0]), "+f"(c[1]), "+f"(c[2]), "+f"(c[3])
        : "r"(a[0]), "r"(a[1]), "r"(a[2]), "r"(a[3]), "r"(b0), "r"(b1));
}
__device__ __forceinline__ void bsplit(float v, bf16& h, bf16& l) {
    h = __float2bfloat16(v);
    l = __float2bfloat16(v - __bfloat162float(h));
}

// ---------------- LayerNorm -> bf16 hi/lo split ----------------
__global__ void __launch_bounds__(256) ln_kernel(
    const float* __restrict__ x, const float* __restrict__ g,
    const float* __restrict__ be, bf16* __restrict__ ohi, bf16* __restrict__ olo)
{
    int row = blockIdx.x;
    int t = threadIdx.x;
    float4 xv = reinterpret_cast<const float4*>(x + (size_t)row * Cc)[t];
    float s  = xv.x + xv.y + xv.z + xv.w;
    float s2 = xv.x*xv.x + xv.y*xv.y + xv.z*xv.z + xv.w*xv.w;
    #pragma unroll
    for (int off = 16; off > 0; off >>= 1) {
        s  += __shfl_xor_sync(0xffffffffu, s,  off);
        s2 += __shfl_xor_sync(0xffffffffu, s2, off);
    }
    __shared__ float ss[8], ss2[8];
    int w = t >> 5, lane = t & 31;
    if (lane == 0) { ss[w] = s; ss2[w] = s2; }
    __syncthreads();
    if (w == 0) {
        s  = (lane < 8) ? ss[lane]  : 0.f;
        s2 = (lane < 8) ? ss2[lane] : 0.f;
        #pragma unroll
        for (int off = 4; off > 0; off >>= 1) {
            s  += __shfl_xor_sync(0xffffffffu, s,  off);
            s2 += __shfl_xor_sync(0xffffffffu, s2, off);
        }
        if (lane == 0) { ss[0] = s; ss2[0] = s2; }
    }
    __syncthreads();
    float mu  = ss[0] * (1.f / Cc);
    float var = ss2[0] * (1.f / Cc) - mu * mu;
    float inv = rsqrtf(var + 1e-5f);
    float4 gv = reinterpret_cast<const float4*>(g)[t];
    float4 bv = reinterpret_cast<const float4*>(be)[t];
    float o0 = (xv.x - mu) * inv * gv.x + bv.x;
    float o1 = (xv.y - mu) * inv * gv.y + bv.y;
    float o2 = (xv.z - mu) * inv * gv.z + bv.z;
    float o3 = (xv.w - mu) * inv * gv.w + bv.w;
    bf16 h0, l0, h1, l1, h2, l2, h3, l3;
    bsplit(o0, h0, l0); bsplit(o1, h1, l1);
    bsplit(o2, h2, l2); bsplit(o3, h3, l3);
    size_t base = (size_t)row * Cc + t * 4;
    __nv_bfloat162* ph = reinterpret_cast<__nv_bfloat162*>(ohi + base);
    __nv_bfloat162* pl = reinterpret_cast<__nv_bfloat162*>(olo + base);
    ph[0] = __nv_bfloat162(h0, h1); ph[1] = __nv_bfloat162(h2, h3);
    pl[0] = __nv_bfloat162(l0, l1); pl[1] = __nv_bfloat162(l2, l3);
}

// ---------------- weight transpose + split: W[K,N] -> WT hi/lo [N,K] --------
__global__ void __launch_bounds__(256) wsplit_kernel(
    const float* __restrict__ W, int K, int N,
    bf16* __restrict__ Thi, bf16* __restrict__ Tlo)
{
    __shared__ float ts[32][33];
    int k0 = blockIdx.y * 32, n0 = blockIdx.x * 32;
    int tx = threadIdx.x & 31, ty = threadIdx.x >> 5;
    #pragma unroll
    for (int r = 0; r < 32; r += 8)
        ts[ty + r][tx] = W[(size_t)(k0 + ty + r) * N + n0 + tx];
    __syncthreads();
    #pragma unroll
    for (int r = 0; r < 32; r += 8) {
        float v = ts[tx][ty + r];
        bf16 h, l;
        bsplit(v, h, l);
        size_t idx = (size_t)(n0 + ty + r) * K + k0 + tx;
        Thi[idx] = h;
        Tlo[idx] = l;
    }
}

// ---------------- bf16x3 tensor-core GEMM (mma.sync) ----------------
// C[m,n] = sum_k A[m,k]*BT[n,k],  A=Ahi+Alo, BT=Bhi+Blo (bf16)
#define BM 128
#define BN 128
#define BK 32
#define NSTG 3
#define LDS 80            // smem row stride bytes (32 bf16 = 64B used + 16 pad)
#define TSZ (128*LDS)     // 10240 bytes per tensor per stage
#define STG_SZ (4*TSZ)    // 40960

#define EPI_QKV   0
#define EPI_RESID 1
#define EPI_RELUS 2

template<int MODE>
__global__ void __launch_bounds__(256, 1)
tgemm_kernel(int M, int N, int K,
             const bf16* __restrict__ Ahi, const bf16* __restrict__ Alo,
             const bf16* __restrict__ Bhi, const bf16* __restrict__ Blo,
             const float* __restrict__ bias, const float* __restrict__ res,
             float* __restrict__ out, bf16* __restrict__ outh, bf16* __restrict__ outl)
{
    extern __shared__ char smem[];
    uint32_t sb = smem_u32(smem);
    int tid = threadIdx.x;
    int w = tid >> 5, l = tid & 31;
    int wm = w >> 2, wn = w & 3;          // 2 x 4 warp grid; warp tile 64x32
    int m0 = blockIdx.y * BM, n0 = blockIdx.x * BN;

    // cp.async producer mapping: chunk c -> row=c>>2, cc=c&3 (16B each)
    int ldrow = tid >> 2, ldcc = tid & 3;

    float acc[4][4][4];
    #pragma unroll
    for (int i = 0; i < 4; i++)
        #pragma unroll
        for (int j = 0; j < 4; j++)
            #pragma unroll
            for (int r = 0; r < 4; r++) acc[i][j][r] = 0.f;

    int NT = K / BK;

    auto load_stage = [&](int t) {
        int kk = t * BK;
        uint32_t sbase = sb + (t % NSTG) * STG_SZ;
        #pragma unroll
        for (int i = 0; i < 2; i++) {
            int row = ldrow + i * 64;
            uint32_t so = row * LDS + ldcc * 16;
            size_t ga = (size_t)(m0 + row) * K + kk + ldcc * 8;
            size_t gb = (size_t)(n0 + row) * K + kk + ldcc * 8;
            cpasync16(sbase + 0 * TSZ + so, Ahi + ga);
            cpasync16(sbase + 1 * TSZ + so, Alo + ga);
            cpasync16(sbase + 2 * TSZ + so, Bhi + gb);
            cpasync16(sbase + 3 * TSZ + so, Blo + gb);
        }
        cp_commit();
    };

    load_stage(0);
    load_stage(1);

    for (int t = 0; t < NT; t++) {
        asm volatile("cp.async.wait_group 1;" ::: "memory");
        __syncthreads();
        if (t + 2 < NT) load_stage(t + 2);

        uint32_t sbase = sb + (t % NSTG) * STG_SZ;
        #pragma unroll
        for (int h = 0; h < 2; h++) {           // two k16 halves of BK=32
            uint32_t ah[4][4], al[4][4], bh[4][2], bl[4][2];
            #pragma unroll
            for (int mi = 0; mi < 4; mi++) {
                uint32_t aaddr = sbase + (uint32_t)(wm * 64 + mi * 16 + (l & 15)) * LDS
                               + h * 32 + (l >> 4) * 16;
                ldsm4(ah[mi][0], ah[mi][1], ah[mi][2], ah[mi][3], aaddr);
                ldsm4(al[mi][0], al[mi][1], al[mi][2], al[mi][3], aaddr + TSZ);
            }
            #pragma unroll
            for (int p = 0; p < 2; p++) {
                int nrow = wn * 32 + p * 16 + ((l >> 4) & 1) * 8 + (l & 7);
                uint32_t baddr = sbase + 2 * TSZ + (uint32_t)nrow * LDS
                               + h * 32 + ((l >> 3) & 1) * 16;
                ldsm4(bh[2*p][0], bh[2*p][1], bh[2*p+1][0], bh[2*p+1][1], baddr);
                ldsm4(bl[2*p][0], bl[2*p][1], bl[2*p+1][0], bl[2*p+1][1], baddr + TSZ);
            }
            #pragma unroll
            for (int mi = 0; mi < 4; mi++)
                #pragma unroll
                for (int ni = 0; ni < 4; ni++) {
                    mma16816(acc[mi][ni], ah[mi], bh[ni][0], bh[ni][1]);
                    mma16816(acc[mi][ni], ah[mi], bl[ni][0], bl[ni][1]);
                    mma16816(acc[mi][ni], al[mi], bh[ni][0], bh[ni][1]);
                }
        }
    }

    // ---------------- epilogue ----------------
    #pragma unroll
    for (int mi = 0; mi < 4; mi++) {
        #pragma unroll
        for (int ni = 0; ni < 4; ni++) {
            int r0 = m0 + wm * 64 + mi * 16 + (l >> 2);
            int c  = n0 + wn * 32 + ni * 8 + (l & 3) * 2;
            #pragma unroll
            for (int hfl = 0; hfl < 2; hfl++) {
                int r = r0 + hfl * 8;
                float v0 = acc[mi][ni][hfl * 2 + 0];
                float v1 = acc[mi][ni][hfl * 2 + 1];
                if (MODE == EPI_QKV) {
                    int b = r / Tt, tt = r % Tt;
                    int hh = c >> 6, d = c & 63;
                    float2 o2 = make_float2(v0, v1);
                    *reinterpret_cast<float2*>(
                        out + (((size_t)(b * Hh + hh) * Tt) + tt) * DHd + d) = o2;
                } else if (MODE == EPI_RESID) {
                    size_t idx = (size_t)r * N + c;
                    float2 bi = *reinterpret_cast<const float2*>(bias + c);
                    float2 rs = *reinterpret_cast<const float2*>(res + idx);
                    *reinterpret_cast<float2*>(out + idx) =
                        make_float2(v0 + bi.x + rs.x, v1 + bi.y + rs.y);
                } else {  // EPI_RELUS
                    size_t idx = (size_t)r * N + c;
                    float2 bi = *reinterpret_cast<const float2*>(bias + c);
                    float a0 = fmaxf(v0 + bi.x, 0.f);
                    float a1 = fmaxf(v1 + bi.y, 0.f);
                    bf16 h0, l0, h1, l1;
                    bsplit(a0, h0, l0);
                    bsplit(a1, h1, l1);
                    *reinterpret_cast<__nv_bfloat162*>(outh + idx) = __nv_bfloat162(h0, h1);
                    *reinterpret_cast<__nv_bfloat162*>(outl + idx) = __nv_bfloat162(l0, l1);
                }
            }
        }
    }
}

// ---------------- Flash attention (fp32), writes bf16 hi/lo ----------------
__global__ void __launch_bounds__(256) attn_kernel(
    const float* __restrict__ q, const float* __restrict__ k,
    const float* __restrict__ v, bf16* __restrict__ ohi, bf16* __restrict__ olo)
{
    extern __shared__ float sm[];
    const int LD = 65;
    float* Qs = sm;
    float* Ks = Qs + 64 * LD;
    float* Vs = Ks + 64 * LD;
    float* Ps = Vs + 64 * LD;

    int qt = blockIdx.x, h = blockIdx.y, b = blockIdx.z;
    int tid = threadIdx.x;
    int r = tid >> 2, cg = tid & 3;
    int qglob = qt * 64 + r;
    size_t bh_row0 = (size_t)(b * Hh + h) * Tt;

    #pragma unroll
    for (int rep = 0; rep < 4; rep++) {
        int idx = rep * 256 + tid;
        int lr = idx >> 4, lc = (idx & 15) * 4;
        float4 qv = *reinterpret_cast<const float4*>(
            q + (bh_row0 + (size_t)qt * 64 + lr) * DHd + lc);
        Qs[lr * LD + lc + 0] = qv.x; Qs[lr * LD + lc + 1] = qv.y;
        Qs[lr * LD + lc + 2] = qv.z; Qs[lr * LD + lc + 3] = qv.w;
    }

    float m_i = -INFINITY, l_i = 0.f;
    float o[16];
    #pragma unroll
    for (int jj = 0; jj < 16; jj++) o[jj] = 0.f;
    const float scale = 0.125f;

    for (int j = 0; j <= qt; j++) {
        __syncthreads();
        #pragma unroll
        for (int rep = 0; rep < 4; rep++) {
            int idx = rep * 256 + tid;
            int lr = idx >> 4, lc = (idx & 15) * 4;
            size_t grow = (bh_row0 + (size_t)j * 64 + lr) * DHd + lc;
            float4 kv = *reinterpret_cast<const float4*>(k + grow);
            float4 vv = *reinterpret_cast<const float4*>(v + grow);
            Ks[lr * LD + lc + 0] = kv.x; Ks[lr * LD + lc + 1] = kv.y;
            Ks[lr * LD + lc + 2] = kv.z; Ks[lr * LD + lc + 3] = kv.w;
            Vs[lr * LD + lc + 0] = vv.x; Vs[lr * LD + lc + 1] = vv.y;
            Vs[lr * LD + lc + 2] = vv.z; Vs[lr * LD + lc + 3] = vv.w;
        }
        __syncthreads();

        float svals[16];
        #pragma unroll
        for (int jj = 0; jj < 16; jj++) svals[jj] = 0.f;
        #pragma unroll 4
        for (int d = 0; d < 64; d++) {
            float qv = Qs[r * LD + d];
            #pragma unroll
            for (int jj = 0; jj < 16; jj++)
                svals[jj] += qv * Ks[(cg * 16 + jj) * LD + d];
        }

        int kbase = j * 64;
        float tmax = -INFINITY;
        #pragma unroll
        for (int jj = 0; jj < 16; jj++) {
            int c = cg * 16 + jj;
            if (kbase + c > qglob) svals[jj] = -INFINITY;
            else                   svals[jj] *= scale;
            tmax = fmaxf(tmax, svals[jj]);
        }
        tmax = fmaxf(tmax, __shfl_xor_sync(0xffffffffu, tmax, 1));
        tmax = fmaxf(tmax, __shfl_xor_sync(0xffffffffu, tmax, 2));

        float m_new = fmaxf(m_i, tmax);
        float alpha = __expf(m_i - m_new);
        float psum = 0.f;
        #pragma unroll
        for (int jj = 0; jj < 16; jj++) {
            float p = __expf(svals[jj] - m_new);
            psum += p;
            Ps[r * LD + cg * 16 + jj] = p;
        }
        psum += __shfl_xor_sync(0xffffffffu, psum, 1);
        psum += __shfl_xor_sync(0xffffffffu, psum, 2);
        l_i = l_i * alpha + psum;
        m_i = m_new;
        __syncwarp();

        #pragma unroll
        for (int jj = 0; jj < 16; jj++) o[jj] *= alpha;
        #pragma unroll 4
        for (int s = 0; s < 64; s++) {
            float p = Ps[r * LD + s];
            #pragma unroll
            for (int jj = 0; jj < 16; jj++)
                o[jj] += p * Vs[s * LD + cg * 16 + jj];
        }
    }

    float invl = 1.f / l_i;
    size_t obase = ((size_t)b * Tt + qglob) * Cc + h * DHd + cg * 16;
    #pragma unroll
    for (int jj2 = 0; jj2 < 8; jj2++) {
        float v0 = o[jj2 * 2 + 0] * invl;
        float v1 = o[jj2 * 2 + 1] * invl;
        bf16 h0, l0, h1, l1;
        bsplit(v0, h0, l0);
        bsplit(v1, h1, l1);
        *reinterpret_cast<__nv_bfloat162*>(ohi + obase + jj2 * 2) = __nv_bfloat162(h0, h1);
        *reinterpret_cast<__nv_bfloat162*>(olo + obase + jj2 * 2) = __nv_bfloat162(l0, l1);
    }
}

// ---------------- launch ----------------
extern "C" void kernel_launch(void* const* d_in, const int* in_sizes, int n_in,
                              void* d_out, int out_size)
{
    const float* x   = (const float*)d_in[0];
    const float* Wq  = (const float*)d_in[1];
    const float* Wk  = (const float*)d_in[2];
    const float* Wv  = (const float*)d_in[3];
    const float* Wp  = (const float*)d_in[4];
    const float* bp  = (const float*)d_in[5];
    const float* W1  = (const float*)d_in[6];
    const float* b1  = (const float*)d_in[7];
    const float* W2  = (const float*)d_in[8];
    const float* b2  = (const float*)d_in[9];
    const float* g1  = (const float*)d_in[10];
    const float* be1 = (const float*)d_in[11];
    const float* g2  = (const float*)d_in[12];
    const float* be2 = (const float*)d_in[13];
    float* out = (float*)d_out;

    bf16 *h_hi, *h_lo, *a_hi, *a_lo, *f_hi, *f_lo;
    float *q, *k, *v;
    bf16 *wqh, *wql, *wkh, *wkl, *wvh, *wvl, *wph, *wpl, *w1h, *w1l, *w2h, *w2l;
    cudaGetSymbolAddress((void**)&h_hi, g_h_hi);
    cudaGetSymbolAddress((void**)&h_lo, g_h_lo);
    cudaGetSymbolAddress((void**)&q,    g_q);
    cudaGetSymbolAddress((void**)&k,    g_k);
    cudaGetSymbolAddress((void**)&v,    g_v);
    cudaGetSymbolAddress((void**)&a_hi, g_attn_hi);
    cudaGetSymbolAddress((void**)&a_lo, g_attn_lo);
    cudaGetSymbolAddress((void**)&f_hi, g_ff_hi);
    cudaGetSymbolAddress((void**)&f_lo, g_ff_lo);
    cudaGetSymbolAddress((void**)&wqh, g_WqT_hi); cudaGetSymbolAddress((void**)&wql, g_WqT_lo);
    cudaGetSymbolAddress((void**)&wkh, g_WkT_hi); cudaGetSymbolAddress((void**)&wkl, g_WkT_lo);
    cudaGetSymbolAddress((void**)&wvh, g_WvT_hi); cudaGetSymbolAddress((void**)&wvl, g_WvT_lo);
    cudaGetSymbolAddress((void**)&wph, g_WpT_hi); cudaGetSymbolAddress((void**)&wpl, g_WpT_lo);
    cudaGetSymbolAddress((void**)&w1h, g_W1T_hi); cudaGetSymbolAddress((void**)&w1l, g_W1T_lo);
    cudaGetSymbolAddress((void**)&w2h, g_W2T_hi); cudaGetSymbolAddress((void**)&w2l, g_W2T_lo);

    const int smem_attn = 4 * 64 * 65 * sizeof(float);
    const int smem_gemm = NSTG * STG_SZ;   // 122880
    cudaFuncSetAttribute(attn_kernel,
                         cudaFuncAttributeMaxDynamicSharedMemorySize, smem_attn);
    cudaFuncSetAttribute(tgemm_kernel<EPI_QKV>,
                         cudaFuncAttributeMaxDynamicSharedMemorySize, smem_gemm);
    cudaFuncSetAttribute(tgemm_kernel<EPI_RESID>,
                         cudaFuncAttributeMaxDynamicSharedMemorySize, smem_gemm);
    cudaFuncSetAttribute(tgemm_kernel<EPI_RELUS>,
                         cudaFuncAttributeMaxDynamicSharedMemorySize, smem_gemm);

    // weight transpose + split
    wsplit_kernel<<<dim3(Cc / 32, Cc / 32),  256>>>(Wq, Cc,  Cc,  wqh, wql);
    wsplit_kernel<<<dim3(Cc / 32, Cc / 32),  256>>>(Wk, Cc,  Cc,  wkh, wkl);
    wsplit_kernel<<<dim3(Cc / 32, Cc / 32),  256>>>(Wv, Cc,  Cc,  wvh, wvl);
    wsplit_kernel<<<dim3(Cc / 32, Cc / 32),  256>>>(Wp, Cc,  Cc,  wph, wpl);
    wsplit_kernel<<<dim3(FFd / 32, Cc / 32), 256>>>(W1, Cc,  FFd, w1h, w1l);
    wsplit_kernel<<<dim3(Cc / 32, FFd / 32), 256>>>(W2, FFd, Cc,  w2h, w2l);

    dim3 gC(Cc / BN, MM / BM);    // (8, 64)
    dim3 gF(FFd / BN, MM / BM);   // (32, 64)

    // 1. LN1 -> bf16 split
    ln_kernel<<<MM, 256>>>(x, g1, be1, h_hi, h_lo);
    // 2. QKV projections (tensor cores, scatter to [B,H,T,DH] fp32)
    tgemm_kernel<EPI_QKV><<<gC, 256, smem_gemm>>>(MM, Cc, Cc, h_hi, h_lo, wqh, wql,
                                                  nullptr, nullptr, q, nullptr, nullptr);
    tgemm_kernel<EPI_QKV><<<gC, 256, smem_gemm>>>(MM, Cc, Cc, h_hi, h_lo, wkh, wkl,
                                                  nullptr, nullptr, k, nullptr, nullptr);
    tgemm_kernel<EPI_QKV><<<gC, 256, smem_gemm>>>(MM, Cc, Cc, h_hi, h_lo, wvh, wvl,
                                                  nullptr, nullptr, v, nullptr, nullptr);
    // 3. attention -> bf16 split
    attn_kernel<<<dim3(Tt / 64, Hh, Bz), 256, smem_attn>>>(q, k, v, a_hi, a_lo);
    // 4. out projection + bias + residual (fp32 out)
    tgemm_kernel<EPI_RESID><<<gC, 256, smem_gemm>>>(MM, Cc, Cc, a_hi, a_lo, wph, wpl,
                                                    bp, x, out, nullptr, nullptr);
    // 5. LN2 -> bf16 split
    ln_kernel<<<MM, 256>>>(out, g2, be2, h_hi, h_lo);
    // 6. MLP up + ReLU -> bf16 split
    tgemm_kernel<EPI_RELUS><<<gF, 256, smem_gemm>>>(MM, FFd, Cc, h_hi, h_lo, w1h, w1l,
                                                    b1, nullptr, nullptr, f_hi, f_lo);
    // 7. MLP down + bias + residual (fp32 out, in-place residual same-thread safe)
    tgemm_kernel<EPI_RESID><<<gC, 256, smem_gemm>>>(MM, Cc, FFd, f_hi, f_lo, w2h, w2l,
                                                    b2, out, out, nullptr, nullptr);
}

// round 4
// speedup vs baseline: 4.5562x; 3.0164x over previous
#include <cuda_runtime.h>
#include <cuda_bf16.h>
#include <math.h>
#include <stdint.h>

// Problem dims (fixed)
#define Bz 4
#define Tt 2048
#define Cc 1024
#define Hh 16
#define DHd 64
#define MM (Bz*Tt)      // 8192
#define FFd (4*Cc)      // 4096

typedef __nv_bfloat16 bf16;

// ---------------- scratch ----------------
__device__ bf16  g_h_hi[(size_t)MM * Cc];
__device__ bf16  g_h_lo[(size_t)MM * Cc];
__device__ bf16  g_qh[(size_t)MM * Cc], g_ql[(size_t)MM * Cc];   // [B,H,T,DH]
__device__ bf16  g_kh[(size_t)MM * Cc], g_kl[(size_t)MM * Cc];
__device__ bf16  g_vh[(size_t)MM * Cc], g_vl[(size_t)MM * Cc];
__device__ bf16  g_attn_hi[(size_t)MM * Cc];
__device__ bf16  g_attn_lo[(size_t)MM * Cc];
__device__ bf16  g_ff_hi[(size_t)MM * FFd];
__device__ bf16  g_ff_lo[(size_t)MM * FFd];
// transposed + split weights [N, K]
__device__ bf16 g_WqT_hi[(size_t)Cc * Cc],  g_WqT_lo[(size_t)Cc * Cc];
__device__ bf16 g_WkT_hi[(size_t)Cc * Cc],  g_WkT_lo[(size_t)Cc * Cc];
__device__ bf16 g_WvT_hi[(size_t)Cc * Cc],  g_WvT_lo[(size_t)Cc * Cc];
__device__ bf16 g_WpT_hi[(size_t)Cc * Cc],  g_WpT_lo[(size_t)Cc * Cc];
__device__ bf16 g_W1T_hi[(size_t)FFd * Cc], g_W1T_lo[(size_t)FFd * Cc];
__device__ bf16 g_W2T_hi[(size_t)Cc * FFd], g_W2T_lo[(size_t)Cc * FFd];

// ---------------- helpers ----------------
__device__ __forceinline__ uint32_t smem_u32(const void* p) {
    uint32_t a;
    asm("{ .reg .u64 t; cvta.to.shared.u64 t, %1; cvt.u32.u64 %0, t; }"
        : "=r"(a) : "l"(p));
    return a;
}
__device__ __forceinline__ void cpasync16(uint32_t s, const void* g) {
    asm volatile("cp.async.cg.shared.global [%0], [%1], 16;" :: "r"(s), "l"(g));
}
__device__ __forceinline__ void cp_commit() {
    asm volatile("cp.async.commit_group;" ::: "memory");
}
__device__ __forceinline__ void ldsm4(uint32_t& r0, uint32_t& r1, uint32_t& r2,
                                      uint32_t& r3, uint32_t a) {
    asm volatile("ldmatrix.sync.aligned.m8n8.x4.shared.b16 {%0,%1,%2,%3}, [%4];"
                 : "=r"(r0), "=r"(r1), "=r"(r2), "=r"(r3) : "r"(a));
}
__device__ __forceinline__ void ldsm4t(uint32_t& r0, uint32_t& r1, uint32_t& r2,
                                       uint32_t& r3, uint32_t a) {
    asm volatile("ldmatrix.sync.aligned.m8n8.x4.trans.shared.b16 {%0,%1,%2,%3}, [%4];"
                 : "=r"(r0), "=r"(r1), "=r"(r2), "=r"(r3) : "r"(a));
}
__device__ __forceinline__ void mma16816(float* c, const uint32_t* a,
                                         uint32_t b0, uint32_t b1) {
    asm volatile(
        "mma.sync.aligned.m16n8k16.row.col.f32.bf16.bf16.f32 "
        "{%0,%1,%2,%3}, {%4,%5,%6,%7}, {%8,%9}, {%0,%1,%2,%3};"
        : "+f"(c[0]), "+f"(c[1]), "+f"(c[2]), "+f"(c[3])
        : "r"(a[0]), "r"(a[1]), "r"(a[2]), "r"(a[3]), "r"(b0), "r"(b1));
}
__device__ __forceinline__ void bsplit(float v, bf16& h, bf16& l) {
    h = __float2bfloat16(v);
    l = __float2bfloat16(v - __bfloat162float(h));
}
// pack two floats into bf16x2 hi and lo words
__device__ __forceinline__ void split2(float a, float b, uint32_t& hi, uint32_t& lo) {
    bf16 ah, al, bh, bl;
    bsplit(a, ah, al);
    bsplit(b, bh, bl);
    __nv_bfloat162 h2(ah, bh), l2(al, bl);
    hi = *reinterpret_cast<uint32_t*>(&h2);
    lo = *reinterpret_cast<uint32_t*>(&l2);
}

// ---------------- LayerNorm -> bf16 hi/lo split ----------------
__global__ void __launch_bounds__(256) ln_kernel(
    const float* __restrict__ x, const float* __restrict__ g,
    const float* __restrict__ be, bf16* __restrict__ ohi, bf16* __restrict__ olo)
{
    int row = blockIdx.x;
    int t = threadIdx.x;
    float4 xv = reinterpret_cast<const float4*>(x + (size_t)row * Cc)[t];
    float s  = xv.x + xv.y + xv.z + xv.w;
    float s2 = xv.x*xv.x + xv.y*xv.y + xv.z*xv.z + xv.w*xv.w;
    #pragma unroll
    for (int off = 16; off > 0; off >>= 1) {
        s  += __shfl_xor_sync(0xffffffffu, s,  off);
        s2 += __shfl_xor_sync(0xffffffffu, s2, off);
    }
    __shared__ float ss[8], ss2[8];
    int w = t >> 5, lane = t & 31;
    if (lane == 0) { ss[w] = s; ss2[w] = s2; }
    __syncthreads();
    if (w == 0) {
        s  = (lane < 8) ? ss[lane]  : 0.f;
        s2 = (lane < 8) ? ss2[lane] : 0.f;
        #pragma unroll
        for (int off = 4; off > 0; off >>= 1) {
            s  += __shfl_xor_sync(0xffffffffu, s,  off);
            s2 += __shfl_xor_sync(0xffffffffu, s2, off);
        }
        if (lane == 0) { ss[0] = s; ss2[0] = s2; }
    }
    __syncthreads();
    float mu  = ss[0] * (1.f / Cc);
    float var = ss2[0] * (1.f / Cc) - mu * mu;
    float inv = rsqrtf(var + 1e-5f);
    float4 gv = reinterpret_cast<const float4*>(g)[t];
    float4 bv = reinterpret_cast<const float4*>(be)[t];
    float o0 = (xv.x - mu) * inv * gv.x + bv.x;
    float o1 = (xv.y - mu) * inv * gv.y + bv.y;
    float o2 = (xv.z - mu) * inv * gv.z + bv.z;
    float o3 = (xv.w - mu) * inv * gv.w + bv.w;
    uint32_t h01, l01, h23, l23;
    split2(o0, o1, h01, l01);
    split2(o2, o3, h23, l23);
    size_t base = (size_t)row * Cc + t * 4;
    uint32_t* ph = reinterpret_cast<uint32_t*>(ohi + base);
    uint32_t* pl = reinterpret_cast<uint32_t*>(olo + base);
    ph[0] = h01; ph[1] = h23;
    pl[0] = l01; pl[1] = l23;
}

// ---------------- weight transpose + split: W[K,N] -> WT hi/lo [N,K] --------
__global__ void __launch_bounds__(256) wsplit_kernel(
    const float* __restrict__ W, int K, int N,
    bf16* __restrict__ Thi, bf16* __restrict__ Tlo)
{
    __shared__ float ts[32][33];
    int k0 = blockIdx.y * 32, n0 = blockIdx.x * 32;
    int tx = threadIdx.x & 31, ty = threadIdx.x >> 5;
    #pragma unroll
    for (int r = 0; r < 32; r += 8)
        ts[ty + r][tx] = W[(size_t)(k0 + ty + r) * N + n0 + tx];
    __syncthreads();
    #pragma unroll
    for (int r = 0; r < 32; r += 8) {
        float v = ts[tx][ty + r];
        bf16 h, l;
        bsplit(v, h, l);
        size_t idx = (size_t)(n0 + ty + r) * K + k0 + tx;
        Thi[idx] = h;
        Tlo[idx] = l;
    }
}

// ---------------- bf16x3 tensor-core GEMM (mma.sync) ----------------
// C[m,n] = sum_k A[m,k]*BT[n,k],  A=Ahi+Alo, BT=Bhi+Blo (bf16)
#define BM 128
#define BN 256
#define BK 32
#define NSTG 3
#define LDS 80              // smem row stride bytes (64B data + 16 pad)
#define TSZ_A (128*LDS)     // 10240
#define TSZ_B (256*LDS)     // 20480
#define SA_HI 0
#define SA_LO TSZ_A
#define SB_HI (2*TSZ_A)
#define SB_LO (2*TSZ_A + TSZ_B)
#define STG_SZ (2*TSZ_A + 2*TSZ_B)   // 61440

#define EPI_QKVS  0
#define EPI_RESID 1
#define EPI_RELUS 2

template<int MODE>
__global__ void __launch_bounds__(256, 1)
tgemm_kernel(int M, int N, int K,
             const bf16* __restrict__ Ahi, const bf16* __restrict__ Alo,
             const bf16* __restrict__ Bhi, const bf16* __restrict__ Blo,
             const float* __restrict__ bias, const float* __restrict__ res,
             float* __restrict__ out, bf16* __restrict__ outh, bf16* __restrict__ outl)
{
    extern __shared__ char smem[];
    uint32_t sb = smem_u32(smem);
    int tid = threadIdx.x;
    int w = tid >> 5, l = tid & 31;
    int wm = w >> 2, wn = w & 3;          // 2 x 4 warp grid; warp tile 64x64
    int m0 = blockIdx.y * BM, n0 = blockIdx.x * BN;

    float acc[4][8][4];
    #pragma unroll
    for (int i = 0; i < 4; i++)
        #pragma unroll
        for (int j = 0; j < 8; j++)
            #pragma unroll
            for (int r = 0; r < 4; r++) acc[i][j][r] = 0.f;

    int NT = K / BK;

    auto load_stage = [&](int t) {
        int kk = t * BK;
        uint32_t sbase = sb + (t % NSTG) * STG_SZ;
        // A: 512 chunks of 16B (hi & lo)
        #pragma unroll
        for (int i = 0; i < 2; i++) {
            int c = tid + 256 * i;
            int row = c >> 2, col = c & 3;
            uint32_t so = row * LDS + col * 16;
            size_t ga = (size_t)(m0 + row) * K + kk + col * 8;
            cpasync16(sbase + SA_HI + so, Ahi + ga);
            cpasync16(sbase + SA_LO + so, Alo + ga);
        }
        // B: 1024 chunks (hi & lo)
        #pragma unroll
        for (int i = 0; i < 4; i++) {
            int c = tid + 256 * i;
            int row = c >> 2, col = c & 3;
            uint32_t so = row * LDS + col * 16;
            size_t gb = (size_t)(n0 + row) * K + kk + col * 8;
            cpasync16(sbase + SB_HI + so, Bhi + gb);
            cpasync16(sbase + SB_LO + so, Blo + gb);
        }
        cp_commit();
    };

    load_stage(0);
    load_stage(1);

    for (int t = 0; t < NT; t++) {
        asm volatile("cp.async.wait_group 1;" ::: "memory");
        __syncthreads();
        if (t + 2 < NT) load_stage(t + 2);

        uint32_t sbase = sb + (t % NSTG) * STG_SZ;
        #pragma unroll
        for (int hk = 0; hk < 2; hk++) {        // two k16 halves of BK=32
            uint32_t ah[4][4], al[4][4];
            #pragma unroll
            for (int mi = 0; mi < 4; mi++) {
                uint32_t aaddr = sbase + SA_HI
                               + (uint32_t)(wm * 64 + mi * 16 + (l & 15)) * LDS
                               + hk * 32 + (l >> 4) * 16;
                ldsm4(ah[mi][0], ah[mi][1], ah[mi][2], ah[mi][3], aaddr);
                ldsm4(al[mi][0], al[mi][1], al[mi][2], al[mi][3], aaddr + TSZ_A);
            }
            #pragma unroll
            for (int p = 0; p < 4; p++) {
                uint32_t bh[4], bl[4];
                uint32_t baddr = sbase + SB_HI
                               + (uint32_t)(wn * 64 + p * 16 + ((l >> 4) & 1) * 8 + (l & 7)) * LDS
                               + hk * 32 + ((l >> 3) & 1) * 16;
                ldsm4(bh[0], bh[1], bh[2], bh[3], baddr);
                ldsm4(bl[0], bl[1], bl[2], bl[3], baddr + TSZ_B);
                #pragma unroll
                for (int mi = 0; mi < 4; mi++) {
                    mma16816(acc[mi][2*p],   ah[mi], bh[0], bh[1]);
                    mma16816(acc[mi][2*p],   ah[mi], bl[0], bl[1]);
                    mma16816(acc[mi][2*p],   al[mi], bh[0], bh[1]);
                    mma16816(acc[mi][2*p+1], ah[mi], bh[2], bh[3]);
                    mma16816(acc[mi][2*p+1], ah[mi], bl[2], bl[3]);
                    mma16816(acc[mi][2*p+1], al[mi], bh[2], bh[3]);
                }
            }
        }
    }

    // ---------------- epilogue ----------------
    #pragma unroll
    for (int mi = 0; mi < 4; mi++) {
        #pragma unroll
        for (int ni = 0; ni < 8; ni++) {
            int r0 = m0 + wm * 64 + mi * 16 + (l >> 2);
            int c  = n0 + wn * 64 + ni * 8 + (l & 3) * 2;
            #pragma unroll
            for (int hfl = 0; hfl < 2; hfl++) {
                int r = r0 + hfl * 8;
                float v0 = acc[mi][ni][hfl * 2 + 0];
                float v1 = acc[mi][ni][hfl * 2 + 1];
                if (MODE == EPI_QKVS) {
                    int b = r / Tt, tt = r % Tt;
                    int hh = c >> 6, d = c & 63;
                    size_t idx = (((size_t)(b * Hh + hh) * Tt) + tt) * DHd + d;
                    uint32_t hi, lo;
                    split2(v0, v1, hi, lo);
                    *reinterpret_cast<uint32_t*>(outh + idx) = hi;
                    *reinterpret_cast<uint32_t*>(outl + idx) = lo;
                } else if (MODE == EPI_RESID) {
                    size_t idx = (size_t)r * N + c;
                    float2 bi = *reinterpret_cast<const float2*>(bias + c);
                    float2 rs = *reinterpret_cast<const float2*>(res + idx);
                    *reinterpret_cast<float2*>(out + idx) =
                        make_float2(v0 + bi.x + rs.x, v1 + bi.y + rs.y);
                } else {  // EPI_RELUS
                    size_t idx = (size_t)r * N + c;
                    float2 bi = *reinterpret_cast<const float2*>(bias + c);
                    float a0 = fmaxf(v0 + bi.x, 0.f);
                    float a1 = fmaxf(v1 + bi.y, 0.f);
                    uint32_t hi, lo;
                    split2(a0, a1, hi, lo);
                    *reinterpret_cast<uint32_t*>(outh + idx) = hi;
                    *reinterpret_cast<uint32_t*>(outl + idx) = lo;
                }
            }
        }
    }
}

// ---------------- Flash attention, mma.sync bf16x3 ----------------
// Block: 128 threads (4 warps), 64 query rows (warp w owns rows w*16..+15).
// Grid: (T/64, H, B). Q frags in registers; K/V double-buffered cp.async.
#define ALD 144                  // smem row stride bytes for 64 bf16 + pad
#define AQH 0
#define AQL (64*ALD)             // 9216
#define AKV0 (2*64*ALD)          // 18432
#define KVSTG (4*64*ALD)         // 36864 per stage (KH,KL,VH,VL)
#define AT_SMEM (AKV0 + 2*KVSTG) // 92160

__global__ void __launch_bounds__(128, 1) attn_kernel(
    const bf16* __restrict__ qh, const bf16* __restrict__ ql,
    const bf16* __restrict__ kh, const bf16* __restrict__ kl,
    const bf16* __restrict__ vh, const bf16* __restrict__ vl,
    bf16* __restrict__ ohi, bf16* __restrict__ olo)
{
    extern __shared__ char smem[];
    uint32_t sb = smem_u32(smem);
    int qt = blockIdx.x, hd = blockIdx.y, b = blockIdx.z;
    int tid = threadIdx.x;
    int w = tid >> 5, l = tid & 31;
    size_t bh_row0 = (size_t)(b * Hh + hd) * Tt;
    int qrow0 = qt * 64 + w * 16;

    // ---- load Q tile (hi/lo) into smem, then ldmatrix into registers ----
    #pragma unroll
    for (int i = 0; i < 4; i++) {
        int c = tid + 128 * i;
        int row = c >> 3, col = c & 7;
        size_t g = (bh_row0 + (size_t)qt * 64 + row) * DHd + col * 8;
        uint32_t so = row * ALD + col * 16;
        *reinterpret_cast<float4*>(smem + AQH + so) =
            *reinterpret_cast<const float4*>(qh + g);
        *reinterpret_cast<float4*>(smem + AQL + so) =
            *reinterpret_cast<const float4*>(ql + g);
    }
    __syncthreads();
    uint32_t qfh[4][4], qfl[4][4];
    #pragma unroll
    for (int ks = 0; ks < 4; ks++) {
        uint32_t qaddr = sb + AQH + (uint32_t)(w * 16 + (l & 15)) * ALD
                       + ks * 32 + (l >> 4) * 16;
        ldsm4(qfh[ks][0], qfh[ks][1], qfh[ks][2], qfh[ks][3], qaddr);
        ldsm4(qfl[ks][0], qfl[ks][1], qfl[ks][2], qfl[ks][3], qaddr + AQL);
    }

    auto load_kv = [&](int j) {
        uint32_t sbase = sb + AKV0 + (j & 1) * KVSTG;
        #pragma unroll
        for (int i = 0; i < 4; i++) {
            int c = tid + 128 * i;
            int row = c >> 3, col = c & 7;
            size_t g = (bh_row0 + (size_t)j * 64 + row) * DHd + col * 8;
            uint32_t so = row * ALD + col * 16;
            cpasync16(sbase + 0 * 9216 + so, kh + g);
            cpasync16(sbase + 1 * 9216 + so, kl + g);
            cpasync16(sbase + 2 * 9216 + so, vh + g);
            cpasync16(sbase + 3 * 9216 + so, vl + g);
        }
        cp_commit();
    };

    load_kv(0);

    float m0r = -INFINITY, m1r = -INFINITY, l0r = 0.f, l1r = 0.f;
    float oacc[8][4];
    #pragma unroll
    for (int i = 0; i < 8; i++)
        #pragma unroll
        for (int c = 0; c < 4; c++) oacc[i][c] = 0.f;

    const float scale = 0.125f;

    for (int j = 0; j <= qt; j++) {
        if (j < qt) {
            load_kv(j + 1);
            asm volatile("cp.async.wait_group 1;" ::: "memory");
        } else {
            asm volatile("cp.async.wait_group 0;" ::: "memory");
        }
        __syncthreads();

        uint32_t sbase = sb + AKV0 + (j & 1) * KVSTG;

        // ---- S = Q K^T ----
        float sacc[8][4];
        #pragma unroll
        for (int i = 0; i < 8; i++)
            #pragma unroll
            for (int c = 0; c < 4; c++) sacc[i][c] = 0.f;

        #pragma unroll
        for (int ks = 0; ks < 4; ks++) {
            #pragma unroll
            for (int p = 0; p < 4; p++) {
                uint32_t kfh[4], kfl[4];
                uint32_t kaddr = sbase
                    + (uint32_t)(p * 16 + ((l >> 4) & 1) * 8 + (l & 7)) * ALD
                    + ks * 32 + ((l >> 3) & 1) * 16;
                ldsm4(kfh[0], kfh[1], kfh[2], kfh[3], kaddr);
                ldsm4(kfl[0], kfl[1], kfl[2], kfl[3], kaddr + 9216);
                mma16816(sacc[2*p],   qfh[ks], kfh[0], kfh[1]);
                mma16816(sacc[2*p],   qfh[ks], kfl[0], kfl[1]);
                mma16816(sacc[2*p],   qfl[ks], kfh[0], kfh[1]);
                mma16816(sacc[2*p+1], qfh[ks], kfh[2], kfh[3]);
                mma16816(sacc[2*p+1], qfh[ks], kfl[2], kfl[3]);
                mma16816(sacc[2*p+1], qfl[ks], kfh[2], kfh[3]);
            }
        }

        // ---- softmax (online) ----
        int jbase = j * 64;
        bool diag = (j == qt);
        float mx0 = -INFINITY, mx1 = -INFINITY;
        #pragma unroll
        for (int ni = 0; ni < 8; ni++) {
            #pragma unroll
            for (int c = 0; c < 4; c++) {
                float s = sacc[ni][c] * scale;
                if (diag) {
                    int col = jbase + ni * 8 + (l & 3) * 2 + (c & 1);
                    int rg  = qrow0 + (l >> 2) + (c >> 1) * 8;
                    if (col > rg) s = -INFINITY;
                }
                sacc[ni][c] = s;
                if (c < 2) mx0 = fmaxf(mx0, s);
                else       mx1 = fmaxf(mx1, s);
            }
        }
        mx0 = fmaxf(mx0, __shfl_xor_sync(0xffffffffu, mx0, 1));
        mx0 = fmaxf(mx0, __shfl_xor_sync(0xffffffffu, mx0, 2));
        mx1 = fmaxf(mx1, __shfl_xor_sync(0xffffffffu, mx1, 1));
        mx1 = fmaxf(mx1, __shfl_xor_sync(0xffffffffu, mx1, 2));

        float mn0 = fmaxf(m0r, mx0), mn1 = fmaxf(m1r, mx1);
        float al0 = __expf(m0r - mn0), al1 = __expf(m1r - mn1);
        float ps0 = 0.f, ps1 = 0.f;
        #pragma unroll
        for (int ni = 0; ni < 8; ni++) {
            float p0 = __expf(sacc[ni][0] - mn0);
            float p1 = __expf(sacc[ni][1] - mn0);
            float p2 = __expf(sacc[ni][2] - mn1);
            float p3 = __expf(sacc[ni][3] - mn1);
            sacc[ni][0] = p0; sacc[ni][1] = p1;
            sacc[ni][2] = p2; sacc[ni][3] = p3;
            ps0 += p0 + p1; ps1 += p2 + p3;
        }
        ps0 += __shfl_xor_sync(0xffffffffu, ps0, 1);
        ps0 += __shfl_xor_sync(0xffffffffu, ps0, 2);
        ps1 += __shfl_xor_sync(0xffffffffu, ps1, 1);
        ps1 += __shfl_xor_sync(0xffffffffu, ps1, 2);
        l0r = l0r * al0 + ps0;
        l1r = l1r * al1 + ps1;
        m0r = mn0; m1r = mn1;

        #pragma unroll
        for (int ni = 0; ni < 8; ni++) {
            oacc[ni][0] *= al0; oacc[ni][1] *= al0;
            oacc[ni][2] *= al1; oacc[ni][3] *= al1;
        }

        // ---- O += P V ----
        #pragma unroll
        for (int ks = 0; ks < 4; ks++) {
            uint32_t aH[4], aL[4];
            split2(sacc[2*ks][0],   sacc[2*ks][1],   aH[0], aL[0]);
            split2(sacc[2*ks][2],   sacc[2*ks][3],   aH[1], aL[1]);
            split2(sacc[2*ks+1][0], sacc[2*ks+1][1], aH[2], aL[2]);
            split2(sacc[2*ks+1][2], sacc[2*ks+1][3], aH[3], aL[3]);
            #pragma unroll
            for (int p = 0; p < 4; p++) {
                uint32_t vfh[4], vfl[4];
                uint32_t vaddr = sbase + 2 * 9216
                    + (uint32_t)(ks * 16 + (l & 15)) * ALD
                    + p * 32 + (l >> 4) * 16;
                ldsm4t(vfh[0], vfh[1], vfh[2], vfh[3], vaddr);
                ldsm4t(vfl[0], vfl[1], vfl[2], vfl[3], vaddr + 9216);
                mma16816(oacc[2*p],   aH, vfh[0], vfh[1]);
                mma16816(oacc[2*p],   aH, vfl[0], vfl[1]);
                mma16816(oacc[2*p],   aL, vfh[0], vfh[1]);
                mma16816(oacc[2*p+1], aH, vfh[2], vfh[3]);
                mma16816(oacc[2*p+1], aH, vfl[2], vfl[3]);
                mma16816(oacc[2*p+1], aL, vfh[2], vfh[3]);
            }
        }
        __syncthreads();   // done reading this KV buffer
    }

    // ---- write out [B,T,C] bf16 hi/lo ----
    float inv0 = 1.f / l0r, inv1 = 1.f / l1r;
    #pragma unroll
    for (int ni = 0; ni < 8; ni++) {
        int col = hd * DHd + ni * 8 + (l & 3) * 2;
        #pragma unroll
        for (int hfl = 0; hfl < 2; hfl++) {
            int rg = qrow0 + (l >> 2) + hfl * 8;
            float inv = hfl ? inv1 : inv0;
            float v0 = oacc[ni][hfl * 2 + 0] * inv;
            float v1 = oacc[ni][hfl * 2 + 1] * inv;
            size_t idx = ((size_t)b * Tt + rg) * Cc + col;
            uint32_t hi, lo;
            split2(v0, v1, hi, lo);
            *reinterpret_cast<uint32_t*>(ohi + idx) = hi;
            *reinterpret_cast<uint32_t*>(olo + idx) = lo;
        }
    }
}

// ---------------- launch ----------------
extern "C" void kernel_launch(void* const* d_in, const int* in_sizes, int n_in,
                              void* d_out, int out_size)
{
    const float* x   = (const float*)d_in[0];
    const float* Wq  = (const float*)d_in[1];
    const float* Wk  = (const float*)d_in[2];
    const float* Wv  = (const float*)d_in[3];
    const float* Wp  = (const float*)d_in[4];
    const float* bp  = (const float*)d_in[5];
    const float* W1  = (const float*)d_in[6];
    const float* b1  = (const float*)d_in[7];
    const float* W2  = (const float*)d_in[8];
    const float* b2  = (const float*)d_in[9];
    const float* g1  = (const float*)d_in[10];
    const float* be1 = (const float*)d_in[11];
    const float* g2  = (const float*)d_in[12];
    const float* be2 = (const float*)d_in[13];
    float* out = (float*)d_out;

    bf16 *h_hi, *h_lo, *a_hi, *a_lo, *f_hi, *f_lo;
    bf16 *qh, *ql, *kh, *kl, *vh, *vl;
    bf16 *wqh, *wql, *wkh, *wkl, *wvh, *wvl, *wph, *wpl, *w1h, *w1l, *w2h, *w2l;
    cudaGetSymbolAddress((void**)&h_hi, g_h_hi);
    cudaGetSymbolAddress((void**)&h_lo, g_h_lo);
    cudaGetSymbolAddress((void**)&qh, g_qh); cudaGetSymbolAddress((void**)&ql, g_ql);
    cudaGetSymbolAddress((void**)&kh, g_kh); cudaGetSymbolAddress((void**)&kl, g_kl);
    cudaGetSymbolAddress((void**)&vh, g_vh); cudaGetSymbolAddress((void**)&vl, g_vl);
    cudaGetSymbolAddress((void**)&a_hi, g_attn_hi);
    cudaGetSymbolAddress((void**)&a_lo, g_attn_lo);
    cudaGetSymbolAddress((void**)&f_hi, g_ff_hi);
    cudaGetSymbolAddress((void**)&f_lo, g_ff_lo);
    cudaGetSymbolAddress((void**)&wqh, g_WqT_hi); cudaGetSymbolAddress((void**)&wql, g_WqT_lo);
    cudaGetSymbolAddress((void**)&wkh, g_WkT_hi); cudaGetSymbolAddress((void**)&wkl, g_WkT_lo);
    cudaGetSymbolAddress((void**)&wvh, g_WvT_hi); cudaGetSymbolAddress((void**)&wvl, g_WvT_lo);
    cudaGetSymbolAddress((void**)&wph, g_WpT_hi); cudaGetSymbolAddress((void**)&wpl, g_WpT_lo);
    cudaGetSymbolAddress((void**)&w1h, g_W1T_hi); cudaGetSymbolAddress((void**)&w1l, g_W1T_lo);
    cudaGetSymbolAddress((void**)&w2h, g_W2T_hi); cudaGetSymbolAddress((void**)&w2l, g_W2T_lo);

    const int smem_gemm = NSTG * STG_SZ;   // 184320
    cudaFuncSetAttribute(attn_kernel,
                         cudaFuncAttributeMaxDynamicSharedMemorySize, AT_SMEM);
    cudaFuncSetAttribute(tgemm_kernel<EPI_QKVS>,
                         cudaFuncAttributeMaxDynamicSharedMemorySize, smem_gemm);
    cudaFuncSetAttribute(tgemm_kernel<EPI_RESID>,
                         cudaFuncAttributeMaxDynamicSharedMemorySize, smem_gemm);
    cudaFuncSetAttribute(tgemm_kernel<EPI_RELUS>,
                         cudaFuncAttributeMaxDynamicSharedMemorySize, smem_gemm);

    // weight transpose + split
    wsplit_kernel<<<dim3(Cc / 32, Cc / 32),  256>>>(Wq, Cc,  Cc,  wqh, wql);
    wsplit_kernel<<<dim3(Cc / 32, Cc / 32),  256>>>(Wk, Cc,  Cc,  wkh, wkl);
    wsplit_kernel<<<dim3(Cc / 32, Cc / 32),  256>>>(Wv, Cc,  Cc,  wvh, wvl);
    wsplit_kernel<<<dim3(Cc / 32, Cc / 32),  256>>>(Wp, Cc,  Cc,  wph, wpl);
    wsplit_kernel<<<dim3(FFd / 32, Cc / 32), 256>>>(W1, Cc,  FFd, w1h, w1l);
    wsplit_kernel<<<dim3(Cc / 32, FFd / 32), 256>>>(W2, FFd, Cc,  w2h, w2l);

    dim3 gC(Cc / BN, MM / BM);    // (4, 64)
    dim3 gF(FFd / BN, MM / BM);   // (16, 64)

    // 1. LN1 -> bf16 split
    ln_kernel<<<MM, 256>>>(x, g1, be1, h_hi, h_lo);
    // 2. QKV projections -> bf16 hi/lo [B,H,T,DH]
    tgemm_kernel<EPI_QKVS><<<gC, 256, smem_gemm>>>(MM, Cc, Cc, h_hi, h_lo, wqh, wql,
                                                   nullptr, nullptr, nullptr, qh, ql);
    tgemm_kernel<EPI_QKVS><<<gC, 256, smem_gemm>>>(MM, Cc, Cc, h_hi, h_lo, wkh, wkl,
                                                   nullptr, nullptr, nullptr, kh, kl);
    tgemm_kernel<EPI_QKVS><<<gC, 256, smem_gemm>>>(MM, Cc, Cc, h_hi, h_lo, wvh, wvl,
                                                   nullptr, nullptr, nullptr, vh, vl);
    // 3. tensor-core flash attention -> bf16 hi/lo [B,T,C]
    attn_kernel<<<dim3(Tt / 64, Hh, Bz), 128, AT_SMEM>>>(qh, ql, kh, kl, vh, vl,
                                                         a_hi, a_lo);
    // 4. out projection + bias + residual (fp32 out)
    tgemm_kernel<EPI_RESID><<<gC, 256, smem_gemm>>>(MM, Cc, Cc, a_hi, a_lo, wph, wpl,
                                                    bp, x, out, nullptr, nullptr);
    // 5. LN2 -> bf16 split
    ln_kernel<<<MM, 256>>>(out, g2, be2, h_hi, h_lo);
    // 6. MLP up + ReLU -> bf16 split
    tgemm_kernel<EPI_RELUS><<<gF, 256, smem_gemm>>>(MM, FFd, Cc, h_hi, h_lo, w1h, w1l,
                                                    b1, nullptr, nullptr, f_hi, f_lo);
    // 7. MLP down + bias + residual (fp32 out)
    tgemm_kernel<EPI_RESID><<<gC, 256, smem_gemm>>>(MM, Cc, FFd, f_hi, f_lo, w2h, w2l,
                                                    b2, out, out, nullptr, nullptr);
}

// round 5
// speedup vs baseline: 4.9462x; 1.0856x over previous
#include <cuda_runtime.h>
#include <cuda_bf16.h>
#include <math.h>
#include <stdint.h>

// Problem dims (fixed)
#define Bz 4
#define Tt 2048
#define Cc 1024
#define Hh 16
#define DHd 64
#define MM (Bz*Tt)      // 8192
#define FFd (4*Cc)      // 4096

typedef __nv_bfloat16 bf16;

// ---------------- scratch ----------------
__device__ bf16  g_h_hi[(size_t)MM * Cc];
__device__ bf16  g_h_lo[(size_t)MM * Cc];
__device__ bf16  g_qkvh[(size_t)3 * MM * Cc];   // q|k|v  each [B,H,T,DH]
__device__ bf16  g_qkvl[(size_t)3 * MM * Cc];
__device__ bf16  g_attn_hi[(size_t)MM * Cc];
__device__ bf16  g_attn_lo[(size_t)MM * Cc];
__device__ bf16  g_ff_hi[(size_t)MM * FFd];
__device__ bf16  g_ff_lo[(size_t)MM * FFd];
// transposed + split weights [N, K]
__device__ bf16 g_WqkvT_hi[(size_t)3 * Cc * Cc], g_WqkvT_lo[(size_t)3 * Cc * Cc];
__device__ bf16 g_WpT_hi[(size_t)Cc * Cc],  g_WpT_lo[(size_t)Cc * Cc];
__device__ bf16 g_W1T_hi[(size_t)FFd * Cc], g_W1T_lo[(size_t)FFd * Cc];
__device__ bf16 g_W2T_hi[(size_t)Cc * FFd], g_W2T_lo[(size_t)Cc * FFd];

// ---------------- helpers ----------------
__device__ __forceinline__ uint32_t smem_u32(const void* p) {
    uint32_t a;
    asm("{ .reg .u64 t; cvta.to.shared.u64 t, %1; cvt.u32.u64 %0, t; }"
        : "=r"(a) : "l"(p));
    return a;
}
__device__ __forceinline__ void cpasync16(uint32_t s, const void* g) {
    asm volatile("cp.async.cg.shared.global [%0], [%1], 16;" :: "r"(s), "l"(g));
}
__device__ __forceinline__ void cp_commit() {
    asm volatile("cp.async.commit_group;" ::: "memory");
}
__device__ __forceinline__ void ldsm4(uint32_t& r0, uint32_t& r1, uint32_t& r2,
                                      uint32_t& r3, uint32_t a) {
    asm volatile("ldmatrix.sync.aligned.m8n8.x4.shared.b16 {%0,%1,%2,%3}, [%4];"
                 : "=r"(r0), "=r"(r1), "=r"(r2), "=r"(r3) : "r"(a));
}
__device__ __forceinline__ void ldsm4t(uint32_t& r0, uint32_t& r1, uint32_t& r2,
                                       uint32_t& r3, uint32_t a) {
    asm volatile("ldmatrix.sync.aligned.m8n8.x4.trans.shared.b16 {%0,%1,%2,%3}, [%4];"
                 : "=r"(r0), "=r"(r1), "=r"(r2), "=r"(r3) : "r"(a));
}
__device__ __forceinline__ void mma16816(float* c, const uint32_t* a,
                                         uint32_t b0, uint32_t b1) {
    asm volatile(
        "mma.sync.aligned.m16n8k16.row.col.f32.bf16.bf16.f32 "
        "{%0,%1,%2,%3}, {%4,%5,%6,%7}, {%8,%9}, {%0,%1,%2,%3};"
        : "+f"(c[0]), "+f"(c[1]), "+f"(c[2]), "+f"(c[3])
        : "r"(a[0]), "r"(a[1]), "r"(a[2]), "r"(a[3]), "r"(b0), "r"(b1));
}
__device__ __forceinline__ void bsplit(float v, bf16& h, bf16& l) {
    h = __float2bfloat16(v);
    l = __float2bfloat16(v - __bfloat162float(h));
}
__device__ __forceinline__ void split2(float a, float b, uint32_t& hi, uint32_t& lo) {
    bf16 ah, al, bh, bl;
    bsplit(a, ah, al);
    bsplit(b, bh, bl);
    __nv_bfloat162 h2(ah, bh), l2(al, bl);
    hi = *reinterpret_cast<uint32_t*>(&h2);
    lo = *reinterpret_cast<uint32_t*>(&l2);
}

// ---------------- LayerNorm -> bf16 hi/lo split ----------------
__global__ void __launch_bounds__(256) ln_kernel(
    const float* __restrict__ x, const float* __restrict__ g,
    const float* __restrict__ be, bf16* __restrict__ ohi, bf16* __restrict__ olo)
{
    int row = blockIdx.x;
    int t = threadIdx.x;
    float4 xv = reinterpret_cast<const float4*>(x + (size_t)row * Cc)[t];
    float s  = xv.x + xv.y + xv.z + xv.w;
    float s2 = xv.x*xv.x + xv.y*xv.y + xv.z*xv.z + xv.w*xv.w;
    #pragma unroll
    for (int off = 16; off > 0; off >>= 1) {
        s  += __shfl_xor_sync(0xffffffffu, s,  off);
        s2 += __shfl_xor_sync(0xffffffffu, s2, off);
    }
    __shared__ float ss[8], ss2[8];
    int w = t >> 5, lane = t & 31;
    if (lane == 0) { ss[w] = s; ss2[w] = s2; }
    __syncthreads();
    if (w == 0) {
        s  = (lane < 8) ? ss[lane]  : 0.f;
        s2 = (lane < 8) ? ss2[lane] : 0.f;
        #pragma unroll
        for (int off = 4; off > 0; off >>= 1) {
            s  += __shfl_xor_sync(0xffffffffu, s,  off);
            s2 += __shfl_xor_sync(0xffffffffu, s2, off);
        }
        if (lane == 0) { ss[0] = s; ss2[0] = s2; }
    }
    __syncthreads();
    float mu  = ss[0] * (1.f / Cc);
    float var = ss2[0] * (1.f / Cc) - mu * mu;
    float inv = rsqrtf(var + 1e-5f);
    float4 gv = reinterpret_cast<const float4*>(g)[t];
    float4 bv = reinterpret_cast<const float4*>(be)[t];
    float o0 = (xv.x - mu) * inv * gv.x + bv.x;
    float o1 = (xv.y - mu) * inv * gv.y + bv.y;
    float o2 = (xv.z - mu) * inv * gv.z + bv.z;
    float o3 = (xv.w - mu) * inv * gv.w + bv.w;
    uint32_t h01, l01, h23, l23;
    split2(o0, o1, h01, l01);
    split2(o2, o3, h23, l23);
    size_t base = (size_t)row * Cc + t * 4;
    uint32_t* ph = reinterpret_cast<uint32_t*>(ohi + base);
    uint32_t* pl = reinterpret_cast<uint32_t*>(olo + base);
    ph[0] = h01; ph[1] = h23;
    pl[0] = l01; pl[1] = l23;
}

// ---------------- weight transpose + split: W[K,N] -> WT hi/lo [N,K] --------
__global__ void __launch_bounds__(256) wsplit_kernel(
    const float* __restrict__ W, int K, int N,
    bf16* __restrict__ Thi, bf16* __restrict__ Tlo)
{
    __shared__ float ts[32][33];
    int k0 = blockIdx.y * 32, n0 = blockIdx.x * 32;
    int tx = threadIdx.x & 31, ty = threadIdx.x >> 5;
    #pragma unroll
    for (int r = 0; r < 32; r += 8)
        ts[ty + r][tx] = W[(size_t)(k0 + ty + r) * N + n0 + tx];
    __syncthreads();
    #pragma unroll
    for (int r = 0; r < 32; r += 8) {
        float v = ts[tx][ty + r];
        bf16 h, l;
        bsplit(v, h, l);
        size_t idx = (size_t)(n0 + ty + r) * K + k0 + tx;
        Thi[idx] = h;
        Tlo[idx] = l;
    }
}

// ---------------- bf16x3 tensor-core GEMM (mma.sync) ----------------
// C[m,n] = sum_k A[m,k]*BT[n,k],  A=Ahi+Alo, BT=Bhi+Blo (bf16)
#define BM 128
#define BN 256
#define BK 64
#define LDSG 144             // row stride bytes: 128B data + 16 pad
#define TSZ_A (128*LDSG)     // 18432
#define TSZ_B (256*LDSG)     // 36864
#define SA_HI 0
#define SA_LO TSZ_A
#define SB_HI (2*TSZ_A)
#define SB_LO (2*TSZ_A + TSZ_B)
#define STG_SZ (2*TSZ_A + 2*TSZ_B)   // 110592
#define GEMM_SMEM (2*STG_SZ)         // 221184 (2 stages)

#define EPI_QKVS  0
#define EPI_RESID 1
#define EPI_RELUS 2

template<int MODE>
__global__ void __launch_bounds__(256, 1)
tgemm_kernel(int M, int N, int K,
             const bf16* __restrict__ Ahi, const bf16* __restrict__ Alo,
             const bf16* __restrict__ Bhi, const bf16* __restrict__ Blo,
             const float* __restrict__ bias, const float* __restrict__ res,
             float* __restrict__ out, bf16* __restrict__ outh, bf16* __restrict__ outl)
{
    extern __shared__ char smem[];
    uint32_t sb = smem_u32(smem);
    int tid = threadIdx.x;
    int w = tid >> 5, l = tid & 31;
    int wm = w >> 2, wn = w & 3;          // 2 x 4 warp grid; warp tile 64x64
    int m0 = blockIdx.y * BM, n0 = blockIdx.x * BN;

    float acc[4][8][4];
    #pragma unroll
    for (int i = 0; i < 4; i++)
        #pragma unroll
        for (int j = 0; j < 8; j++)
            #pragma unroll
            for (int r = 0; r < 4; r++) acc[i][j][r] = 0.f;

    int NT = K / BK;

    auto load_stage = [&](int t) {
        int kk = t * BK;
        uint32_t sbase = sb + (t & 1) * STG_SZ;
        // A: 1024 chunks of 16B (hi & lo)
        #pragma unroll
        for (int i = 0; i < 4; i++) {
            int c = tid + 256 * i;
            int row = c >> 3, col = c & 7;
            uint32_t so = row * LDSG + col * 16;
            size_t ga = (size_t)(m0 + row) * K + kk + col * 8;
            cpasync16(sbase + SA_HI + so, Ahi + ga);
            cpasync16(sbase + SA_LO + so, Alo + ga);
        }
        // B: 2048 chunks (hi & lo)
        #pragma unroll
        for (int i = 0; i < 8; i++) {
            int c = tid + 256 * i;
            int row = c >> 3, col = c & 7;
            uint32_t so = row * LDSG + col * 16;
            size_t gb = (size_t)(n0 + row) * K + kk + col * 8;
            cpasync16(sbase + SB_HI + so, Bhi + gb);
            cpasync16(sbase + SB_LO + so, Blo + gb);
        }
        cp_commit();
    };

    load_stage(0);
    load_stage(1);

    for (int t = 0; t < NT; t++) {
        if (t < NT - 1) { asm volatile("cp.async.wait_group 1;" ::: "memory"); }
        else            { asm volatile("cp.async.wait_group 0;" ::: "memory"); }
        __syncthreads();

        uint32_t sbase = sb + (t & 1) * STG_SZ;
        #pragma unroll
        for (int hk = 0; hk < 4; hk++) {        // four k16 slices of BK=64
            uint32_t ah[4][4], al[4][4];
            #pragma unroll
            for (int mi = 0; mi < 4; mi++) {
                uint32_t aaddr = sbase + SA_HI
                               + (uint32_t)(wm * 64 + mi * 16 + (l & 15)) * LDSG
                               + hk * 32 + (l >> 4) * 16;
                ldsm4(ah[mi][0], ah[mi][1], ah[mi][2], ah[mi][3], aaddr);
                ldsm4(al[mi][0], al[mi][1], al[mi][2], al[mi][3], aaddr + TSZ_A);
            }
            #pragma unroll
            for (int p = 0; p < 4; p++) {
                uint32_t bh[4], bl[4];
                uint32_t baddr = sbase + SB_HI
                               + (uint32_t)(wn * 64 + p * 16 + ((l >> 4) & 1) * 8 + (l & 7)) * LDSG
                               + hk * 32 + ((l >> 3) & 1) * 16;
                ldsm4(bh[0], bh[1], bh[2], bh[3], baddr);
                ldsm4(bl[0], bl[1], bl[2], bl[3], baddr + TSZ_B);
                #pragma unroll
                for (int mi = 0; mi < 4; mi++) {
                    mma16816(acc[mi][2*p],   ah[mi], bh[0], bh[1]);
                    mma16816(acc[mi][2*p],   ah[mi], bl[0], bl[1]);
                    mma16816(acc[mi][2*p],   al[mi], bh[0], bh[1]);
                    mma16816(acc[mi][2*p+1], ah[mi], bh[2], bh[3]);
                    mma16816(acc[mi][2*p+1], ah[mi], bl[2], bl[3]);
                    mma16816(acc[mi][2*p+1], al[mi], bh[2], bh[3]);
                }
            }
        }
        __syncthreads();
        if (t + 2 < NT) load_stage(t + 2);
    }

    // ---------------- epilogue ----------------
    #pragma unroll
    for (int mi = 0; mi < 4; mi++) {
        #pragma unroll
        for (int ni = 0; ni < 8; ni++) {
            int r0 = m0 + wm * 64 + mi * 16 + (l >> 2);
            int c  = n0 + wn * 64 + ni * 8 + (l & 3) * 2;
            #pragma unroll
            for (int hfl = 0; hfl < 2; hfl++) {
                int r = r0 + hfl * 8;
                float v0 = acc[mi][ni][hfl * 2 + 0];
                float v1 = acc[mi][ni][hfl * 2 + 1];
                if (MODE == EPI_QKVS) {
                    int b = r / Tt, tt = r % Tt;
                    int sel = c >> 10;            // 0=q 1=k 2=v
                    int cc = c & 1023;
                    int hh = cc >> 6, d = cc & 63;
                    size_t idx = (size_t)sel * MM * Cc
                               + (((size_t)(b * Hh + hh) * Tt) + tt) * DHd + d;
                    uint32_t hi, lo;
                    split2(v0, v1, hi, lo);
                    *reinterpret_cast<uint32_t*>(outh + idx) = hi;
                    *reinterpret_cast<uint32_t*>(outl + idx) = lo;
                } else if (MODE == EPI_RESID) {
                    size_t idx = (size_t)r * N + c;
                    float2 bi = *reinterpret_cast<const float2*>(bias + c);
                    float2 rs = *reinterpret_cast<const float2*>(res + idx);
                    *reinterpret_cast<float2*>(out + idx) =
                        make_float2(v0 + bi.x + rs.x, v1 + bi.y + rs.y);
                } else {  // EPI_RELUS
                    size_t idx = (size_t)r * N + c;
                    float2 bi = *reinterpret_cast<const float2*>(bias + c);
                    float a0 = fmaxf(v0 + bi.x, 0.f);
                    float a1 = fmaxf(v1 + bi.y, 0.f);
                    uint32_t hi, lo;
                    split2(a0, a1, hi, lo);
                    *reinterpret_cast<uint32_t*>(outh + idx) = hi;
                    *reinterpret_cast<uint32_t*>(outl + idx) = lo;
                }
            }
        }
    }
}

// ---------------- Flash attention, mma.sync bf16x3 ----------------
#define ALD 144
#define AQH 0
#define AQL (64*ALD)
#define AKV0 (2*64*ALD)
#define KVSTG (4*64*ALD)
#define AT_SMEM (AKV0 + 2*KVSTG)  // 92160

__global__ void __launch_bounds__(128, 1) attn_kernel(
    const bf16* __restrict__ qh, const bf16* __restrict__ ql,
    const bf16* __restrict__ kh, const bf16* __restrict__ kl,
    const bf16* __restrict__ vh, const bf16* __restrict__ vl,
    bf16* __restrict__ ohi, bf16* __restrict__ olo)
{
    extern __shared__ char smem[];
    uint32_t sb = smem_u32(smem);
    int qt = blockIdx.x, hd = blockIdx.y, b = blockIdx.z;
    int tid = threadIdx.x;
    int w = tid >> 5, l = tid & 31;
    size_t bh_row0 = (size_t)(b * Hh + hd) * Tt;
    int qrow0 = qt * 64 + w * 16;

    #pragma unroll
    for (int i = 0; i < 4; i++) {
        int c = tid + 128 * i;
        int row = c >> 3, col = c & 7;
        size_t g = (bh_row0 + (size_t)qt * 64 + row) * DHd + col * 8;
        uint32_t so = row * ALD + col * 16;
        *reinterpret_cast<float4*>(smem + AQH + so) =
            *reinterpret_cast<const float4*>(qh + g);
        *reinterpret_cast<float4*>(smem + AQL + so) =
            *reinterpret_cast<const float4*>(ql + g);
    }
    __syncthreads();
    uint32_t qfh[4][4], qfl[4][4];
    #pragma unroll
    for (int ks = 0; ks < 4; ks++) {
        uint32_t qaddr = sb + AQH + (uint32_t)(w * 16 + (l & 15)) * ALD
                       + ks * 32 + (l >> 4) * 16;
        ldsm4(qfh[ks][0], qfh[ks][1], qfh[ks][2], qfh[ks][3], qaddr);
        ldsm4(qfl[ks][0], qfl[ks][1], qfl[ks][2], qfl[ks][3], qaddr + AQL);
    }

    auto load_kv = [&](int j) {
        uint32_t sbase = sb + AKV0 + (j & 1) * KVSTG;
        #pragma unroll
        for (int i = 0; i < 4; i++) {
            int c = tid + 128 * i;
            int row = c >> 3, col = c & 7;
            size_t g = (bh_row0 + (size_t)j * 64 + row) * DHd + col * 8;
            uint32_t so = row * ALD + col * 16;
            cpasync16(sbase + 0 * 9216 + so, kh + g);
            cpasync16(sbase + 1 * 9216 + so, kl + g);
            cpasync16(sbase + 2 * 9216 + so, vh + g);
            cpasync16(sbase + 3 * 9216 + so, vl + g);
        }
        cp_commit();
    };

    load_kv(0);

    float m0r = -INFINITY, m1r = -INFINITY, l0r = 0.f, l1r = 0.f;
    float oacc[8][4];
    #pragma unroll
    for (int i = 0; i < 8; i++)
        #pragma unroll
        for (int c = 0; c < 4; c++) oacc[i][c] = 0.f;

    const float scale = 0.125f;

    for (int j = 0; j <= qt; j++) {
        if (j < qt) {
            load_kv(j + 1);
            asm volatile("cp.async.wait_group 1;" ::: "memory");
        } else {
            asm volatile("cp.async.wait_group 0;" ::: "memory");
        }
        __syncthreads();

        uint32_t sbase = sb + AKV0 + (j & 1) * KVSTG;

        float sacc[8][4];
        #pragma unroll
        for (int i = 0; i < 8; i++)
            #pragma unroll
            for (int c = 0; c < 4; c++) sacc[i][c] = 0.f;

        #pragma unroll
        for (int ks = 0; ks < 4; ks++) {
            #pragma unroll
            for (int p = 0; p < 4; p++) {
                uint32_t kfh[4], kfl[4];
                uint32_t kaddr = sbase
                    + (uint32_t)(p * 16 + ((l >> 4) & 1) * 8 + (l & 7)) * ALD
                    + ks * 32 + ((l >> 3) & 1) * 16;
                ldsm4(kfh[0], kfh[1], kfh[2], kfh[3], kaddr);
                ldsm4(kfl[0], kfl[1], kfl[2], kfl[3], kaddr + 9216);
                mma16816(sacc[2*p],   qfh[ks], kfh[0], kfh[1]);
                mma16816(sacc[2*p],   qfh[ks], kfl[0], kfl[1]);
                mma16816(sacc[2*p],   qfl[ks], kfh[0], kfh[1]);
                mma16816(sacc[2*p+1], qfh[ks], kfh[2], kfh[3]);
                mma16816(sacc[2*p+1], qfh[ks], kfl[2], kfl[3]);
                mma16816(sacc[2*p+1], qfl[ks], kfh[2], kfh[3]);
            }
        }

        int jbase = j * 64;
        bool diag = (j == qt);
        float mx0 = -INFINITY, mx1 = -INFINITY;
        #pragma unroll
        for (int ni = 0; ni < 8; ni++) {
            #pragma unroll
            for (int c = 0; c < 4; c++) {
                float s = sacc[ni][c] * scale;
                if (diag) {
                    int col = jbase + ni * 8 + (l & 3) * 2 + (c & 1);
                    int rg  = qrow0 + (l >> 2) + (c >> 1) * 8;
                    if (col > rg) s = -INFINITY;
                }
                sacc[ni][c] = s;
                if (c < 2) mx0 = fmaxf(mx0, s);
                else       mx1 = fmaxf(mx1, s);
            }
        }
        mx0 = fmaxf(mx0, __shfl_xor_sync(0xffffffffu, mx0, 1));
        mx0 = fmaxf(mx0, __shfl_xor_sync(0xffffffffu, mx0, 2));
        mx1 = fmaxf(mx1, __shfl_xor_sync(0xffffffffu, mx1, 1));
        mx1 = fmaxf(mx1, __shfl_xor_sync(0xffffffffu, mx1, 2));

        float mn0 = fmaxf(m0r, mx0), mn1 = fmaxf(m1r, mx1);
        float al0 = __expf(m0r - mn0), al1 = __expf(m1r - mn1);
        float ps0 = 0.f, ps1 = 0.f;
        #pragma unroll
        for (int ni = 0; ni < 8; ni++) {
            float p0 = __expf(sacc[ni][0] - mn0);
            float p1 = __expf(sacc[ni][1] - mn0);
            float p2 = __expf(sacc[ni][2] - mn1);
            float p3 = __expf(sacc[ni][3] - mn1);
            sacc[ni][0] = p0; sacc[ni][1] = p1;
            sacc[ni][2] = p2; sacc[ni][3] = p3;
            ps0 += p0 + p1; ps1 += p2 + p3;
        }
        ps0 += __shfl_xor_sync(0xffffffffu, ps0, 1);
        ps0 += __shfl_xor_sync(0xffffffffu, ps0, 2);
        ps1 += __shfl_xor_sync(0xffffffffu, ps1, 1);
        ps1 += __shfl_xor_sync(0xffffffffu, ps1, 2);
        l0r = l0r * al0 + ps0;
        l1r = l1r * al1 + ps1;
        m0r = mn0; m1r = mn1;

        #pragma unroll
        for (int ni = 0; ni < 8; ni++) {
            oacc[ni][0] *= al0; oacc[ni][1] *= al0;
            oacc[ni][2] *= al1; oacc[ni][3] *= al1;
        }

        #pragma unroll
        for (int ks = 0; ks < 4; ks++) {
            uint32_t aH[4], aL[4];
            split2(sacc[2*ks][0],   sacc[2*ks][1],   aH[0], aL[0]);
            split2(sacc[2*ks][2],   sacc[2*ks][3],   aH[1], aL[1]);
            split2(sacc[2*ks+1][0], sacc[2*ks+1][1], aH[2], aL[2]);
            split2(sacc[2*ks+1][2], sacc[2*ks+1][3], aH[3], aL[3]);
            #pragma unroll
            for (int p = 0; p < 4; p++) {
                uint32_t vfh[4], vfl[4];
                uint32_t vaddr = sbase + 2 * 9216
                    + (uint32_t)(ks * 16 + (l & 15)) * ALD
                    + p * 32 + (l >> 4) * 16;
                ldsm4t(vfh[0], vfh[1], vfh[2], vfh[3], vaddr);
                ldsm4t(vfl[0], vfl[1], vfl[2], vfl[3], vaddr + 9216);
                mma16816(oacc[2*p],   aH, vfh[0], vfh[1]);
                mma16816(oacc[2*p],   aH, vfl[0], vfl[1]);
                mma16816(oacc[2*p],   aL, vfh[0], vfh[1]);
                mma16816(oacc[2*p+1], aH, vfh[2], vfh[3]);
                mma16816(oacc[2*p+1], aH, vfl[2], vfl[3]);
                mma16816(oacc[2*p+1], aL, vfh[2], vfh[3]);
            }
        }
        __syncthreads();
    }

    float inv0 = 1.f / l0r, inv1 = 1.f / l1r;
    #pragma unroll
    for (int ni = 0; ni < 8; ni++) {
        int col = hd * DHd + ni * 8 + (l & 3) * 2;
        #pragma unroll
        for (int hfl = 0; hfl < 2; hfl++) {
            int rg = qrow0 + (l >> 2) + hfl * 8;
            float inv = hfl ? inv1 : inv0;
            float v0 = oacc[ni][hfl * 2 + 0] * inv;
            float v1 = oacc[ni][hfl * 2 + 1] * inv;
            size_t idx = ((size_t)b * Tt + rg) * Cc + col;
            uint32_t hi, lo;
            split2(v0, v1, hi, lo);
            *reinterpret_cast<uint32_t*>(ohi + idx) = hi;
            *reinterpret_cast<uint32_t*>(olo + idx) = lo;
        }
    }
}

// ---------------- launch ----------------
extern "C" void kernel_launch(void* const* d_in, const int* in_sizes, int n_in,
                              void* d_out, int out_size)
{
    const float* x   = (const float*)d_in[0];
    const float* Wq  = (const float*)d_in[1];
    const float* Wk  = (const float*)d_in[2];
    const float* Wv  = (const float*)d_in[3];
    const float* Wp  = (const float*)d_in[4];
    const float* bp  = (const float*)d_in[5];
    const float* W1  = (const float*)d_in[6];
    const float* b1  = (const float*)d_in[7];
    const float* W2  = (const float*)d_in[8];
    const float* b2  = (const float*)d_in[9];
    const float* g1  = (const float*)d_in[10];
    const float* be1 = (const float*)d_in[11];
    const float* g2  = (const float*)d_in[12];
    const float* be2 = (const float*)d_in[13];
    float* out = (float*)d_out;

    bf16 *h_hi, *h_lo, *a_hi, *a_lo, *f_hi, *f_lo, *qkvh, *qkvl;
    bf16 *wqkvh, *wqkvl, *wph, *wpl, *w1h, *w1l, *w2h, *w2l;
    cudaGetSymbolAddress((void**)&h_hi, g_h_hi);
    cudaGetSymbolAddress((void**)&h_lo, g_h_lo);
    cudaGetSymbolAddress((void**)&qkvh, g_qkvh);
    cudaGetSymbolAddress((void**)&qkvl, g_qkvl);
    cudaGetSymbolAddress((void**)&a_hi, g_attn_hi);
    cudaGetSymbolAddress((void**)&a_lo, g_attn_lo);
    cudaGetSymbolAddress((void**)&f_hi, g_ff_hi);
    cudaGetSymbolAddress((void**)&f_lo, g_ff_lo);
    cudaGetSymbolAddress((void**)&wqkvh, g_WqkvT_hi);
    cudaGetSymbolAddress((void**)&wqkvl, g_WqkvT_lo);
    cudaGetSymbolAddress((void**)&wph, g_WpT_hi); cudaGetSymbolAddress((void**)&wpl, g_WpT_lo);
    cudaGetSymbolAddress((void**)&w1h, g_W1T_hi); cudaGetSymbolAddress((void**)&w1l, g_W1T_lo);
    cudaGetSymbolAddress((void**)&w2h, g_W2T_hi); cudaGetSymbolAddress((void**)&w2l, g_W2T_lo);

    cudaFuncSetAttribute(attn_kernel,
                         cudaFuncAttributeMaxDynamicSharedMemorySize, AT_SMEM);
    cudaFuncSetAttribute(tgemm_kernel<EPI_QKVS>,
                         cudaFuncAttributeMaxDynamicSharedMemorySize, GEMM_SMEM);
    cudaFuncSetAttribute(tgemm_kernel<EPI_RESID>,
                         cudaFuncAttributeMaxDynamicSharedMemorySize, GEMM_SMEM);
    cudaFuncSetAttribute(tgemm_kernel<EPI_RELUS>,
                         cudaFuncAttributeMaxDynamicSharedMemorySize, GEMM_SMEM);

    dim3 gQKV(3 * Cc / BN, MM / BM);  // (12, 64)
    dim3 gC(Cc / BN, MM / BM);        // (4, 64)
    dim3 gF(FFd / BN, MM / BM);       // (16, 64)

    // Launch order chosen so ncu (-s 5 -c 1) captures the fused QKV GEMM (#6).
    wsplit_kernel<<<dim3(Cc / 32, Cc / 32),  256>>>(Wq, Cc, Cc, wqkvh,            wqkvl);
    wsplit_kernel<<<dim3(Cc / 32, Cc / 32),  256>>>(Wk, Cc, Cc, wqkvh + Cc * Cc,  wqkvl + Cc * Cc);
    wsplit_kernel<<<dim3(Cc / 32, Cc / 32),  256>>>(Wv, Cc, Cc, wqkvh + 2*Cc*Cc,  wqkvl + 2*Cc*Cc);
    wsplit_kernel<<<dim3(Cc / 32, Cc / 32),  256>>>(Wp, Cc, Cc, wph, wpl);
    // 5. LN1
    ln_kernel<<<MM, 256>>>(x, g1, be1, h_hi, h_lo);
    // 6. fused QKV projection (ncu target)
    tgemm_kernel<EPI_QKVS><<<gQKV, 256, GEMM_SMEM>>>(MM, 3 * Cc, Cc, h_hi, h_lo,
                                                     wqkvh, wqkvl,
                                                     nullptr, nullptr, nullptr, qkvh, qkvl);
    // remaining weight splits (needed only before MLP)
    wsplit_kernel<<<dim3(FFd / 32, Cc / 32), 256>>>(W1, Cc,  FFd, w1h, w1l);
    wsplit_kernel<<<dim3(Cc / 32, FFd / 32), 256>>>(W2, FFd, Cc,  w2h, w2l);
    // attention
    attn_kernel<<<dim3(Tt / 64, Hh, Bz), 128, AT_SMEM>>>(
        qkvh, qkvl,
        qkvh + (size_t)MM * Cc, qkvl + (size_t)MM * Cc,
        qkvh + (size_t)2 * MM * Cc, qkvl + (size_t)2 * MM * Cc,
        a_hi, a_lo);
    // out projection + bias + residual
    tgemm_kernel<EPI_RESID><<<gC, 256, GEMM_SMEM>>>(MM, Cc, Cc, a_hi, a_lo, wph, wpl,
                                                    bp, x, out, nullptr, nullptr);
    // LN2
    ln_kernel<<<MM, 256>>>(out, g2, be2, h_hi, h_lo);
    // MLP up + ReLU
    tgemm_kernel<EPI_RELUS><<<gF, 256, GEMM_SMEM>>>(MM, FFd, Cc, h_hi, h_lo, w1h, w1l,
                                                    b1, nullptr, nullptr, f_hi, f_lo);
    // MLP down + bias + residual
    tgemm_kernel<EPI_RESID><<<gC, 256, GEMM_SMEM>>>(MM, Cc, FFd, f_hi, f_lo, w2h, w2l,
                                                    b2, out, out, nullptr, nullptr);
}

// round 6
// speedup vs baseline: 6.0427x; 1.2217x over previous
#include <cuda_runtime.h>
#include <cuda_bf16.h>
#include <cuda_fp16.h>
#include <math.h>
#include <stdint.h>

// Problem dims (fixed)
#define Bz 4
#define Tt 2048
#define Cc 1024
#define Hh 16
#define DHd 64
#define MM (Bz*Tt)      // 8192
#define FFd (4*Cc)      // 4096

typedef __nv_bfloat16 bf16;
typedef __half f16;

// ---------------- scratch ----------------
__device__ bf16  g_h_hi[(size_t)MM * Cc];          // LN1 out (bf16 split, QKV gemm A)
__device__ bf16  g_h_lo[(size_t)MM * Cc];
__device__ bf16  g_qkvh[(size_t)3 * MM * Cc];      // q|k|v  each [B,H,T,DH]
__device__ bf16  g_qkvl[(size_t)3 * MM * Cc];
__device__ f16   g_attn_hi[(size_t)MM * Cc];       // attn out (fp16 split, proj gemm A)
__device__ f16   g_attn_lo[(size_t)MM * Cc];
__device__ f16   g_h2_hi[(size_t)MM * Cc];         // LN2 out (fp16 split)
__device__ f16   g_h2_lo[(size_t)MM * Cc];
__device__ f16   g_ff_hi[(size_t)MM * FFd];        // MLP hidden (fp16 split)
__device__ f16   g_ff_lo[(size_t)MM * FFd];
// transposed weights [N, K]
__device__ bf16 g_WqkvT_hi[(size_t)3 * Cc * Cc], g_WqkvT_lo[(size_t)3 * Cc * Cc];
__device__ f16  g_WpT16[(size_t)Cc * Cc];
__device__ f16  g_W1T16[(size_t)FFd * Cc];
__device__ f16  g_W2T16[(size_t)Cc * FFd];

// ---------------- helpers ----------------
__device__ __forceinline__ uint32_t smem_u32(const void* p) {
    uint32_t a;
    asm("{ .reg .u64 t; cvta.to.shared.u64 t, %1; cvt.u32.u64 %0, t; }"
        : "=r"(a) : "l"(p));
    return a;
}
__device__ __forceinline__ void cpasync16(uint32_t s, const void* g) {
    asm volatile("cp.async.cg.shared.global [%0], [%1], 16;" :: "r"(s), "l"(g));
}
__device__ __forceinline__ void cp_commit() {
    asm volatile("cp.async.commit_group;" ::: "memory");
}
__device__ __forceinline__ void ldsm4(uint32_t& r0, uint32_t& r1, uint32_t& r2,
                                      uint32_t& r3, uint32_t a) {
    asm volatile("ldmatrix.sync.aligned.m8n8.x4.shared.b16 {%0,%1,%2,%3}, [%4];"
                 : "=r"(r0), "=r"(r1), "=r"(r2), "=r"(r3) : "r"(a));
}
__device__ __forceinline__ void ldsm4t(uint32_t& r0, uint32_t& r1, uint32_t& r2,
                                       uint32_t& r3, uint32_t a) {
    asm volatile("ldmatrix.sync.aligned.m8n8.x4.trans.shared.b16 {%0,%1,%2,%3}, [%4];"
                 : "=r"(r0), "=r"(r1), "=r"(r2), "=r"(r3) : "r"(a));
}
__device__ __forceinline__ void mma16816(float* c, const uint32_t* a,
                                         uint32_t b0, uint32_t b1) {
    asm volatile(
        "mma.sync.aligned.m16n8k16.row.col.f32.bf16.bf16.f32 "
        "{%0,%1,%2,%3}, {%4,%5,%6,%7}, {%8,%9}, {%0,%1,%2,%3};"
        : "+f"(c[0]), "+f"(c[1]), "+f"(c[2]), "+f"(c[3])
        : "r"(a[0]), "r"(a[1]), "r"(a[2]), "r"(a[3]), "r"(b0), "r"(b1));
}
__device__ __forceinline__ void mma16816h(float* c, const uint32_t* a,
                                          uint32_t b0, uint32_t b1) {
    asm volatile(
        "mma.sync.aligned.m16n8k16.row.col.f32.f16.f16.f32 "
        "{%0,%1,%2,%3}, {%4,%5,%6,%7}, {%8,%9}, {%0,%1,%2,%3};"
        : "+f"(c[0]), "+f"(c[1]), "+f"(c[2]), "+f"(c[3])
        : "r"(a[0]), "r"(a[1]), "r"(a[2]), "r"(a[3]), "r"(b0), "r"(b1));
}
__device__ __forceinline__ void bsplit(float v, bf16& h, bf16& l) {
    h = __float2bfloat16(v);
    l = __float2bfloat16(v - __bfloat162float(h));
}
__device__ __forceinline__ void split2(float a, float b, uint32_t& hi, uint32_t& lo) {
    bf16 ah, al, bh, bl;
    bsplit(a, ah, al);
    bsplit(b, bh, bl);
    __nv_bfloat162 h2(ah, bh), l2(al, bl);
    hi = *reinterpret_cast<uint32_t*>(&h2);
    lo = *reinterpret_cast<uint32_t*>(&l2);
}
__device__ __forceinline__ void hsplit(float v, f16& h, f16& l) {
    h = __float2half_rn(v);
    l = __float2half_rn(v - __half2float(h));
}
__device__ __forceinline__ void split2h(float a, float b, uint32_t& hi, uint32_t& lo) {
    f16 ah, al, bh, bl;
    hsplit(a, ah, al);
    hsplit(b, bh, bl);
    __half2 h2 = __halves2half2(ah, bh), l2 = __halves2half2(al, bl);
    hi = *reinterpret_cast<uint32_t*>(&h2);
    lo = *reinterpret_cast<uint32_t*>(&l2);
}

// ---------------- LayerNorm -> bf16 hi/lo split ----------------
template<int FP16OUT>
__global__ void __launch_bounds__(256) ln_kernel(
    const float* __restrict__ x, const float* __restrict__ g,
    const float* __restrict__ be, void* __restrict__ ohi_, void* __restrict__ olo_)
{
    int row = blockIdx.x;
    int t = threadIdx.x;
    float4 xv = reinterpret_cast<const float4*>(x + (size_t)row * Cc)[t];
    float s  = xv.x + xv.y + xv.z + xv.w;
    float s2 = xv.x*xv.x + xv.y*xv.y + xv.z*xv.z + xv.w*xv.w;
    #pragma unroll
    for (int off = 16; off > 0; off >>= 1) {
        s  += __shfl_xor_sync(0xffffffffu, s,  off);
        s2 += __shfl_xor_sync(0xffffffffu, s2, off);
    }
    __shared__ float ss[8], ss2[8];
    int w = t >> 5, lane = t & 31;
    if (lane == 0) { ss[w] = s; ss2[w] = s2; }
    __syncthreads();
    if (w == 0) {
        s  = (lane < 8) ? ss[lane]  : 0.f;
        s2 = (lane < 8) ? ss2[lane] : 0.f;
        #pragma unroll
        for (int off = 4; off > 0; off >>= 1) {
            s  += __shfl_xor_sync(0xffffffffu, s,  off);
            s2 += __shfl_xor_sync(0xffffffffu, s2, off);
        }
        if (lane == 0) { ss[0] = s; ss2[0] = s2; }
    }
    __syncthreads();
    float mu  = ss[0] * (1.f / Cc);
    float var = ss2[0] * (1.f / Cc) - mu * mu;
    float inv = rsqrtf(var + 1e-5f);
    float4 gv = reinterpret_cast<const float4*>(g)[t];
    float4 bv = reinterpret_cast<const float4*>(be)[t];
    float o0 = (xv.x - mu) * inv * gv.x + bv.x;
    float o1 = (xv.y - mu) * inv * gv.y + bv.y;
    float o2 = (xv.z - mu) * inv * gv.z + bv.z;
    float o3 = (xv.w - mu) * inv * gv.w + bv.w;
    uint32_t h01, l01, h23, l23;
    if (FP16OUT) { split2h(o0, o1, h01, l01); split2h(o2, o3, h23, l23); }
    else         { split2(o0, o1, h01, l01);  split2(o2, o3, h23, l23); }
    size_t base = (size_t)row * Cc + t * 4;   // element offset (2B elems)
    uint32_t* ph = reinterpret_cast<uint32_t*>((char*)ohi_ + base * 2);
    uint32_t* pl = reinterpret_cast<uint32_t*>((char*)olo_ + base * 2);
    ph[0] = h01; ph[1] = h23;
    pl[0] = l01; pl[1] = l23;
}

// ---------------- weight transpose + split: W[K,N] -> WT hi/lo [N,K] --------
__global__ void __launch_bounds__(256) wsplit_kernel(
    const float* __restrict__ W, int K, int N,
    bf16* __restrict__ Thi, bf16* __restrict__ Tlo)
{
    __shared__ float ts[32][33];
    int k0 = blockIdx.y * 32, n0 = blockIdx.x * 32;
    int tx = threadIdx.x & 31, ty = threadIdx.x >> 5;
    #pragma unroll
    for (int r = 0; r < 32; r += 8)
        ts[ty + r][tx] = W[(size_t)(k0 + ty + r) * N + n0 + tx];
    __syncthreads();
    #pragma unroll
    for (int r = 0; r < 32; r += 8) {
        float v = ts[tx][ty + r];
        bf16 h, l;
        bsplit(v, h, l);
        size_t idx = (size_t)(n0 + ty + r) * K + k0 + tx;
        Thi[idx] = h;
        Tlo[idx] = l;
    }
}

// weight transpose -> single fp16:  W[K,N] -> WT [N,K]
__global__ void __launch_bounds__(256) wsplit16_kernel(
    const float* __restrict__ W, int K, int N, f16* __restrict__ T)
{
    __shared__ float ts[32][33];
    int k0 = blockIdx.y * 32, n0 = blockIdx.x * 32;
    int tx = threadIdx.x & 31, ty = threadIdx.x >> 5;
    #pragma unroll
    for (int r = 0; r < 32; r += 8)
        ts[ty + r][tx] = W[(size_t)(k0 + ty + r) * N + n0 + tx];
    __syncthreads();
    #pragma unroll
    for (int r = 0; r < 32; r += 8)
        T[(size_t)(n0 + ty + r) * K + k0 + tx] = __float2half_rn(ts[tx][ty + r]);
}

// ---------------- shared GEMM geometry ----------------
#define BM 128
#define BN 256
#define BK 64
#define LDSG 144             // row stride bytes: 128B data + 16 pad
#define TSZ_A (128*LDSG)     // 18432
#define TSZ_B (256*LDSG)     // 36864

#define EPI_QKVS  0
#define EPI_RESID 1
#define EPI_RELUS 2

// ======== bf16x3 GEMM (QKV only), 2-stage ========
#define SA_HI 0
#define SA_LO TSZ_A
#define SB_HI (2*TSZ_A)
#define SB_LO (2*TSZ_A + TSZ_B)
#define STG_SZ (2*TSZ_A + 2*TSZ_B)   // 110592
#define GEMM_SMEM (2*STG_SZ)         // 221184

__global__ void __launch_bounds__(256, 1)
tgemm_kernel(int M, int N, int K,
             const bf16* __restrict__ Ahi, const bf16* __restrict__ Alo,
             const bf16* __restrict__ Bhi, const bf16* __restrict__ Blo,
             bf16* __restrict__ outh, bf16* __restrict__ outl)
{
    extern __shared__ char smem[];
    uint32_t sb = smem_u32(smem);
    int tid = threadIdx.x;
    int w = tid >> 5, l = tid & 31;
    int wm = w >> 2, wn = w & 3;
    int m0 = blockIdx.y * BM, n0 = blockIdx.x * BN;

    float acc[4][8][4];
    #pragma unroll
    for (int i = 0; i < 4; i++)
        #pragma unroll
        for (int j = 0; j < 8; j++)
            #pragma unroll
            for (int r = 0; r < 4; r++) acc[i][j][r] = 0.f;

    int NT = K / BK;

    auto load_stage = [&](int t) {
        int kk = t * BK;
        uint32_t sbase = sb + (t & 1) * STG_SZ;
        #pragma unroll
        for (int i = 0; i < 4; i++) {
            int c = tid + 256 * i;
            int row = c >> 3, col = c & 7;
            uint32_t so = row * LDSG + col * 16;
            size_t ga = (size_t)(m0 + row) * K + kk + col * 8;
            cpasync16(sbase + SA_HI + so, Ahi + ga);
            cpasync16(sbase + SA_LO + so, Alo + ga);
        }
        #pragma unroll
        for (int i = 0; i < 8; i++) {
            int c = tid + 256 * i;
            int row = c >> 3, col = c & 7;
            uint32_t so = row * LDSG + col * 16;
            size_t gb = (size_t)(n0 + row) * K + kk + col * 8;
            cpasync16(sbase + SB_HI + so, Bhi + gb);
            cpasync16(sbase + SB_LO + so, Blo + gb);
        }
        cp_commit();
    };

    load_stage(0);
    load_stage(1);

    for (int t = 0; t < NT; t++) {
        if (t < NT - 1) { asm volatile("cp.async.wait_group 1;" ::: "memory"); }
        else            { asm volatile("cp.async.wait_group 0;" ::: "memory"); }
        __syncthreads();

        uint32_t sbase = sb + (t & 1) * STG_SZ;
        #pragma unroll
        for (int hk = 0; hk < 4; hk++) {
            uint32_t ah[4][4], al[4][4];
            #pragma unroll
            for (int mi = 0; mi < 4; mi++) {
                uint32_t aaddr = sbase + SA_HI
                               + (uint32_t)(wm * 64 + mi * 16 + (l & 15)) * LDSG
                               + hk * 32 + (l >> 4) * 16;
                ldsm4(ah[mi][0], ah[mi][1], ah[mi][2], ah[mi][3], aaddr);
                ldsm4(al[mi][0], al[mi][1], al[mi][2], al[mi][3], aaddr + TSZ_A);
            }
            #pragma unroll
            for (int p = 0; p < 4; p++) {
                uint32_t bh[4], bl[4];
                uint32_t baddr = sbase + SB_HI
                               + (uint32_t)(wn * 64 + p * 16 + ((l >> 4) & 1) * 8 + (l & 7)) * LDSG
                               + hk * 32 + ((l >> 3) & 1) * 16;
                ldsm4(bh[0], bh[1], bh[2], bh[3], baddr);
                ldsm4(bl[0], bl[1], bl[2], bl[3], baddr + TSZ_B);
                #pragma unroll
                for (int mi = 0; mi < 4; mi++) {
                    mma16816(acc[mi][2*p],   ah[mi], bh[0], bh[1]);
                    mma16816(acc[mi][2*p],   ah[mi], bl[0], bl[1]);
                    mma16816(acc[mi][2*p],   al[mi], bh[0], bh[1]);
                    mma16816(acc[mi][2*p+1], ah[mi], bh[2], bh[3]);
                    mma16816(acc[mi][2*p+1], ah[mi], bl[2], bl[3]);
                    mma16816(acc[mi][2*p+1], al[mi], bh[2], bh[3]);
                }
            }
        }
        __syncthreads();
        if (t + 2 < NT) load_stage(t + 2);
    }

    // epilogue: QKV scatter, bf16 hi/lo
    #pragma unroll
    for (int mi = 0; mi < 4; mi++) {
        #pragma unroll
        for (int ni = 0; ni < 8; ni++) {
            int r0 = m0 + wm * 64 + mi * 16 + (l >> 2);
            int c  = n0 + wn * 64 + ni * 8 + (l & 3) * 2;
            #pragma unroll
            for (int hfl = 0; hfl < 2; hfl++) {
                int r = r0 + hfl * 8;
                float v0 = acc[mi][ni][hfl * 2 + 0];
                float v1 = acc[mi][ni][hfl * 2 + 1];
                int b = r / Tt, tt = r % Tt;
                int sel = c >> 10;
                int cc = c & 1023;
                int hh = cc >> 6, d = cc & 63;
                size_t idx = (size_t)sel * MM * Cc
                           + (((size_t)(b * Hh + hh) * Tt) + tt) * DHd + d;
                uint32_t hi, lo;
                split2(v0, v1, hi, lo);
                *reinterpret_cast<uint32_t*>(outh + idx) = hi;
                *reinterpret_cast<uint32_t*>(outl + idx) = lo;
            }
        }
    }
}

// ======== fp16 2-term GEMM (proj / MLP), 3-stage ========
#define SA16_HI 0
#define SA16_LO TSZ_A
#define SB16    (2*TSZ_A)
#define STG16   (2*TSZ_A + TSZ_B)    // 73728
#define GEMM16_SMEM (3*STG16)        // 221184

template<int MODE>
__global__ void __launch_bounds__(256, 1)
tgemm16_kernel(int M, int N, int K,
               const f16* __restrict__ Ahi, const f16* __restrict__ Alo,
               const f16* __restrict__ B16,
               const float* __restrict__ bias, const float* __restrict__ res,
               float* __restrict__ out, f16* __restrict__ outh, f16* __restrict__ outl)
{
    extern __shared__ char smem[];
    uint32_t sb = smem_u32(smem);
    int tid = threadIdx.x;
    int w = tid >> 5, l = tid & 31;
    int wm = w >> 2, wn = w & 3;
    int m0 = blockIdx.y * BM, n0 = blockIdx.x * BN;

    float acc[4][8][4];
    #pragma unroll
    for (int i = 0; i < 4; i++)
        #pragma unroll
        for (int j = 0; j < 8; j++)
            #pragma unroll
            for (int r = 0; r < 4; r++) acc[i][j][r] = 0.f;

    int NT = K / BK;

    auto load_stage = [&](int t) {
        int kk = t * BK;
        uint32_t sbase = sb + (t % 3) * STG16;
        #pragma unroll
        for (int i = 0; i < 4; i++) {
            int c = tid + 256 * i;
            int row = c >> 3, col = c & 7;
            uint32_t so = row * LDSG + col * 16;
            size_t ga = (size_t)(m0 + row) * K + kk + col * 8;
            cpasync16(sbase + SA16_HI + so, Ahi + ga);
            cpasync16(sbase + SA16_LO + so, Alo + ga);
        }
        #pragma unroll
        for (int i = 0; i < 8; i++) {
            int c = tid + 256 * i;
            int row = c >> 3, col = c & 7;
            uint32_t so = row * LDSG + col * 16;
            size_t gb = (size_t)(n0 + row) * K + kk + col * 8;
            cpasync16(sbase + SB16 + so, B16 + gb);
        }
        cp_commit();
    };

    load_stage(0);
    load_stage(1);

    for (int t = 0; t < NT; t++) {
        if (t + 1 < NT) { asm volatile("cp.async.wait_group 1;" ::: "memory"); }
        else            { asm volatile("cp.async.wait_group 0;" ::: "memory"); }
        __syncthreads();
        if (t + 2 < NT) load_stage(t + 2);   // writes stage (t-1)%3, reads done

        uint32_t sbase = sb + (t % 3) * STG16;
        #pragma unroll
        for (int hk = 0; hk < 4; hk++) {
            uint32_t ah[4][4], al[4][4];
            #pragma unroll
            for (int mi = 0; mi < 4; mi++) {
                uint32_t aaddr = sbase + SA16_HI
                               + (uint32_t)(wm * 64 + mi * 16 + (l & 15)) * LDSG
                               + hk * 32 + (l >> 4) * 16;
                ldsm4(ah[mi][0], ah[mi][1], ah[mi][2], ah[mi][3], aaddr);
                ldsm4(al[mi][0], al[mi][1], al[mi][2], al[mi][3], aaddr + TSZ_A);
            }
            #pragma unroll
            for (int p = 0; p < 4; p++) {
                uint32_t bh[4];
                uint32_t baddr = sbase + SB16
                               + (uint32_t)(wn * 64 + p * 16 + ((l >> 4) & 1) * 8 + (l & 7)) * LDSG
                               + hk * 32 + ((l >> 3) & 1) * 16;
                ldsm4(bh[0], bh[1], bh[2], bh[3], baddr);
                #pragma unroll
                for (int mi = 0; mi < 4; mi++) {
                    mma16816h(acc[mi][2*p],   ah[mi], bh[0], bh[1]);
                    mma16816h(acc[mi][2*p],   al[mi], bh[0], bh[1]);
                    mma16816h(acc[mi][2*p+1], ah[mi], bh[2], bh[3]);
                    mma16816h(acc[mi][2*p+1], al[mi], bh[2], bh[3]);
                }
            }
        }
    }

    // epilogue
    #pragma unroll
    for (int mi = 0; mi < 4; mi++) {
        #pragma unroll
        for (int ni = 0; ni < 8; ni++) {
            int r0 = m0 + wm * 64 + mi * 16 + (l >> 2);
            int c  = n0 + wn * 64 + ni * 8 + (l & 3) * 2;
            #pragma unroll
            for (int hfl = 0; hfl < 2; hfl++) {
                int r = r0 + hfl * 8;
                float v0 = acc[mi][ni][hfl * 2 + 0];
                float v1 = acc[mi][ni][hfl * 2 + 1];
                if (MODE == EPI_RESID) {
                    size_t idx = (size_t)r * N + c;
                    float2 bi = *reinterpret_cast<const float2*>(bias + c);
                    float2 rs = *reinterpret_cast<const float2*>(res + idx);
                    *reinterpret_cast<float2*>(out + idx) =
                        make_float2(v0 + bi.x + rs.x, v1 + bi.y + rs.y);
                } else {  // EPI_RELUS -> fp16 split
                    size_t idx = (size_t)r * N + c;
                    float2 bi = *reinterpret_cast<const float2*>(bias + c);
                    float a0 = fmaxf(v0 + bi.x, 0.f);
                    float a1 = fmaxf(v1 + bi.y, 0.f);
                    uint32_t hi, lo;
                    split2h(a0, a1, hi, lo);
                    *reinterpret_cast<uint32_t*>(outh + idx) = hi;
                    *reinterpret_cast<uint32_t*>(outl + idx) = lo;
                }
            }
        }
    }
}

// ---------------- Flash attention, mma.sync bf16x3 ----------------
#define ALD 144
#define AQH 0
#define AQL (64*ALD)
#define AKV0 (2*64*ALD)
#define KVSTG (4*64*ALD)
#define AT_SMEM (AKV0 + 2*KVSTG)  // 92160

__global__ void __launch_bounds__(128, 1) attn_kernel(
    const bf16* __restrict__ qh, const bf16* __restrict__ ql,
    const bf16* __restrict__ kh, const bf16* __restrict__ kl,
    const bf16* __restrict__ vh, const bf16* __restrict__ vl,
    f16* __restrict__ ohi, f16* __restrict__ olo)
{
    extern __shared__ char smem[];
    uint32_t sb = smem_u32(smem);
    int qt = gridDim.x - 1 - blockIdx.x;   // LPT: heaviest tiles first
    int hd = blockIdx.y, b = blockIdx.z;
    int tid = threadIdx.x;
    int w = tid >> 5, l = tid & 31;
    size_t bh_row0 = (size_t)(b * Hh + hd) * Tt;
    int qrow0 = qt * 64 + w * 16;

    #pragma unroll
    for (int i = 0; i < 4; i++) {
        int c = tid + 128 * i;
        int row = c >> 3, col = c & 7;
        size_t g = (bh_row0 + (size_t)qt * 64 + row) * DHd + col * 8;
        uint32_t so = row * ALD + col * 16;
        *reinterpret_cast<float4*>(smem + AQH + so) =
            *reinterpret_cast<const float4*>(qh + g);
        *reinterpret_cast<float4*>(smem + AQL + so) =
            *reinterpret_cast<const float4*>(ql + g);
    }
    __syncthreads();
    uint32_t qfh[4][4], qfl[4][4];
    #pragma unroll
    for (int ks = 0; ks < 4; ks++) {
        uint32_t qaddr = sb + AQH + (uint32_t)(w * 16 + (l & 15)) * ALD
                       + ks * 32 + (l >> 4) * 16;
        ldsm4(qfh[ks][0], qfh[ks][1], qfh[ks][2], qfh[ks][3], qaddr);
        ldsm4(qfl[ks][0], qfl[ks][1], qfl[ks][2], qfl[ks][3], qaddr + AQL);
    }

    auto load_kv = [&](int j) {
        uint32_t sbase = sb + AKV0 + (j & 1) * KVSTG;
        #pragma unroll
        for (int i = 0; i < 4; i++) {
            int c = tid + 128 * i;
            int row = c >> 3, col = c & 7;
            size_t g = (bh_row0 + (size_t)j * 64 + row) * DHd + col * 8;
            uint32_t so = row * ALD + col * 16;
            cpasync16(sbase + 0 * 9216 + so, kh + g);
            cpasync16(sbase + 1 * 9216 + so, kl + g);
            cpasync16(sbase + 2 * 9216 + so, vh + g);
            cpasync16(sbase + 3 * 9216 + so, vl + g);
        }
        cp_commit();
    };

    load_kv(0);

    float m0r = -INFINITY, m1r = -INFINITY, l0r = 0.f, l1r = 0.f;
    float oacc[8][4];
    #pragma unroll
    for (int i = 0; i < 8; i++)
        #pragma unroll
        for (int c = 0; c < 4; c++) oacc[i][c] = 0.f;

    const float scale = 0.125f;

    for (int j = 0; j <= qt; j++) {
        if (j < qt) {
            load_kv(j + 1);
            asm volatile("cp.async.wait_group 1;" ::: "memory");
        } else {
            asm volatile("cp.async.wait_group 0;" ::: "memory");
        }
        __syncthreads();

        uint32_t sbase = sb + AKV0 + (j & 1) * KVSTG;

        float sacc[8][4];
        #pragma unroll
        for (int i = 0; i < 8; i++)
            #pragma unroll
            for (int c = 0; c < 4; c++) sacc[i][c] = 0.f;

        #pragma unroll
        for (int ks = 0; ks < 4; ks++) {
            #pragma unroll
            for (int p = 0; p < 4; p++) {
                uint32_t kfh[4], kfl[4];
                uint32_t kaddr = sbase
                    + (uint32_t)(p * 16 + ((l >> 4) & 1) * 8 + (l & 7)) * ALD
                    + ks * 32 + ((l >> 3) & 1) * 16;
                ldsm4(kfh[0], kfh[1], kfh[2], kfh[3], kaddr);
                ldsm4(kfl[0], kfl[1], kfl[2], kfl[3], kaddr + 9216);
                mma16816(sacc[2*p],   qfh[ks], kfh[0], kfh[1]);
                mma16816(sacc[2*p],   qfh[ks], kfl[0], kfl[1]);
                mma16816(sacc[2*p],   qfl[ks], kfh[0], kfh[1]);
                mma16816(sacc[2*p+1], qfh[ks], kfh[2], kfh[3]);
                mma16816(sacc[2*p+1], qfh[ks], kfl[2], kfl[3]);
                mma16816(sacc[2*p+1], qfl[ks], kfh[2], kfh[3]);
            }
        }

        int jbase = j * 64;
        bool diag = (j == qt);
        float mx0 = -INFINITY, mx1 = -INFINITY;
        #pragma unroll
        for (int ni = 0; ni < 8; ni++) {
            #pragma unroll
            for (int c = 0; c < 4; c++) {
                float s = sacc[ni][c] * scale;
                if (diag) {
                    int col = jbase + ni * 8 + (l & 3) * 2 + (c & 1);
                    int rg  = qrow0 + (l >> 2) + (c >> 1) * 8;
                    if (col > rg) s = -INFINITY;
                }
                sacc[ni][c] = s;
                if (c < 2) mx0 = fmaxf(mx0, s);
                else       mx1 = fmaxf(mx1, s);
            }
        }
        mx0 = fmaxf(mx0, __shfl_xor_sync(0xffffffffu, mx0, 1));
        mx0 = fmaxf(mx0, __shfl_xor_sync(0xffffffffu, mx0, 2));
        mx1 = fmaxf(mx1, __shfl_xor_sync(0xffffffffu, mx1, 1));
        mx1 = fmaxf(mx1, __shfl_xor_sync(0xffffffffu, mx1, 2));

        float mn0 = fmaxf(m0r, mx0), mn1 = fmaxf(m1r, mx1);
        float al0 = __expf(m0r - mn0), al1 = __expf(m1r - mn1);
        float ps0 = 0.f, ps1 = 0.f;
        #pragma unroll
        for (int ni = 0; ni < 8; ni++) {
            float p0 = __expf(sacc[ni][0] - mn0);
            float p1 = __expf(sacc[ni][1] - mn0);
            float p2 = __expf(sacc[ni][2] - mn1);
            float p3 = __expf(sacc[ni][3] - mn1);
            sacc[ni][0] = p0; sacc[ni][1] = p1;
            sacc[ni][2] = p2; sacc[ni][3] = p3;
            ps0 += p0 + p1; ps1 += p2 + p3;
        }
        ps0 += __shfl_xor_sync(0xffffffffu, ps0, 1);
        ps0 += __shfl_xor_sync(0xffffffffu, ps0, 2);
        ps1 += __shfl_xor_sync(0xffffffffu, ps1, 1);
        ps1 += __shfl_xor_sync(0xffffffffu, ps1, 2);
        l0r = l0r * al0 + ps0;
        l1r = l1r * al1 + ps1;
        m0r = mn0; m1r = mn1;

        #pragma unroll
        for (int ni = 0; ni < 8; ni++) {
            oacc[ni][0] *= al0; oacc[ni][1] *= al0;
            oacc[ni][2] *= al1; oacc[ni][3] *= al1;
        }

        #pragma unroll
        for (int ks = 0; ks < 4; ks++) {
            uint32_t aH[4], aL[4];
            split2(sacc[2*ks][0],   sacc[2*ks][1],   aH[0], aL[0]);
            split2(sacc[2*ks][2],   sacc[2*ks][3],   aH[1], aL[1]);
            split2(sacc[2*ks+1][0], sacc[2*ks+1][1], aH[2], aL[2]);
            split2(sacc[2*ks+1][2], sacc[2*ks+1][3], aH[3], aL[3]);
            #pragma unroll
            for (int p = 0; p < 4; p++) {
                uint32_t vfh[4], vfl[4];
                uint32_t vaddr = sbase + 2 * 9216
                    + (uint32_t)(ks * 16 + (l & 15)) * ALD
                    + p * 32 + (l >> 4) * 16;
                ldsm4t(vfh[0], vfh[1], vfh[2], vfh[3], vaddr);
                ldsm4t(vfl[0], vfl[1], vfl[2], vfl[3], vaddr + 9216);
                mma16816(oacc[2*p],   aH, vfh[0], vfh[1]);
                mma16816(oacc[2*p],   aH, vfl[0], vfl[1]);
                mma16816(oacc[2*p],   aL, vfh[0], vfh[1]);
                mma16816(oacc[2*p+1], aH, vfh[2], vfh[3]);
                mma16816(oacc[2*p+1], aH, vfl[2], vfl[3]);
                mma16816(oacc[2*p+1], aL, vfh[2], vfh[3]);
            }
        }
        __syncthreads();
    }

    // write out [B,T,C] fp16 hi/lo (proj GEMM input)
    float inv0 = 1.f / l0r, inv1 = 1.f / l1r;
    #pragma unroll
    for (int ni = 0; ni < 8; ni++) {
        int col = hd * DHd + ni * 8 + (l & 3) * 2;
        #pragma unroll
        for (int hfl = 0; hfl < 2; hfl++) {
            int rg = qrow0 + (l >> 2) + hfl * 8;
            float inv = hfl ? inv1 : inv0;
            float v0 = oacc[ni][hfl * 2 + 0] * inv;
            float v1 = oacc[ni][hfl * 2 + 1] * inv;
            size_t idx = ((size_t)b * Tt + rg) * Cc + col;
            uint32_t hi, lo;
            split2h(v0, v1, hi, lo);
            *reinterpret_cast<uint32_t*>(ohi + idx) = hi;
            *reinterpret_cast<uint32_t*>(olo + idx) = lo;
        }
    }
}

// ---------------- launch ----------------
extern "C" void kernel_launch(void* const* d_in, const int* in_sizes, int n_in,
                              void* d_out, int out_size)
{
    const float* x   = (const float*)d_in[0];
    const float* Wq  = (const float*)d_in[1];
    const float* Wk  = (const float*)d_in[2];
    const float* Wv  = (const float*)d_in[3];
    const float* Wp  = (const float*)d_in[4];
    const float* bp  = (const float*)d_in[5];
    const float* W1  = (const float*)d_in[6];
    const float* b1  = (const float*)d_in[7];
    const float* W2  = (const float*)d_in[8];
    const float* b2  = (const float*)d_in[9];
    const float* g1  = (const float*)d_in[10];
    const float* be1 = (const float*)d_in[11];
    const float* g2  = (const float*)d_in[12];
    const float* be2 = (const float*)d_in[13];
    float* out = (float*)d_out;

    bf16 *h_hi, *h_lo, *qkvh, *qkvl, *wqkvh, *wqkvl;
    f16 *a_hi, *a_lo, *h2h, *h2l, *f_hi, *f_lo, *wp16, *w116, *w216;
    cudaGetSymbolAddress((void**)&h_hi, g_h_hi);
    cudaGetSymbolAddress((void**)&h_lo, g_h_lo);
    cudaGetSymbolAddress((void**)&qkvh, g_qkvh);
    cudaGetSymbolAddress((void**)&qkvl, g_qkvl);
    cudaGetSymbolAddress((void**)&a_hi, g_attn_hi);
    cudaGetSymbolAddress((void**)&a_lo, g_attn_lo);
    cudaGetSymbolAddress((void**)&h2h,  g_h2_hi);
    cudaGetSymbolAddress((void**)&h2l,  g_h2_lo);
    cudaGetSymbolAddress((void**)&f_hi, g_ff_hi);
    cudaGetSymbolAddress((void**)&f_lo, g_ff_lo);
    cudaGetSymbolAddress((void**)&wqkvh, g_WqkvT_hi);
    cudaGetSymbolAddress((void**)&wqkvl, g_WqkvT_lo);
    cudaGetSymbolAddress((void**)&wp16, g_WpT16);
    cudaGetSymbolAddress((void**)&w116, g_W1T16);
    cudaGetSymbolAddress((void**)&w216, g_W2T16);

    cudaFuncSetAttribute(attn_kernel,
                         cudaFuncAttributeMaxDynamicSharedMemorySize, AT_SMEM);
    cudaFuncSetAttribute(tgemm_kernel,
                         cudaFuncAttributeMaxDynamicSharedMemorySize, GEMM_SMEM);
    cudaFuncSetAttribute(tgemm16_kernel<EPI_RESID>,
                         cudaFuncAttributeMaxDynamicSharedMemorySize, GEMM16_SMEM);
    cudaFuncSetAttribute(tgemm16_kernel<EPI_RELUS>,
                         cudaFuncAttributeMaxDynamicSharedMemorySize, GEMM16_SMEM);

    dim3 gQKV(3 * Cc / BN, MM / BM);  // (12, 64)
    dim3 gC(Cc / BN, MM / BM);        // (4, 64)
    dim3 gF(FFd / BN, MM / BM);       // (16, 64)

    // weight prep
    wsplit_kernel<<<dim3(Cc / 32, Cc / 32),  256>>>(Wq, Cc, Cc, wqkvh,           wqkvl);
    wsplit_kernel<<<dim3(Cc / 32, Cc / 32),  256>>>(Wk, Cc, Cc, wqkvh + Cc * Cc, wqkvl + Cc * Cc);
    wsplit_kernel<<<dim3(Cc / 32, Cc / 32),  256>>>(Wv, Cc, Cc, wqkvh + 2*Cc*Cc, wqkvl + 2*Cc*Cc);
    wsplit16_kernel<<<dim3(Cc / 32, Cc / 32),  256>>>(Wp, Cc,  Cc,  wp16);
    // LN1 -> bf16 split
    ln_kernel<0><<<MM, 256>>>(x, g1, be1, h_hi, h_lo);
    // fused QKV projection (bf16x3)
    tgemm_kernel<<<gQKV, 256, GEMM_SMEM>>>(MM, 3 * Cc, Cc, h_hi, h_lo,
                                           wqkvh, wqkvl, qkvh, qkvl);
    wsplit16_kernel<<<dim3(FFd / 32, Cc / 32), 256>>>(W1, Cc,  FFd, w116);
    wsplit16_kernel<<<dim3(Cc / 32, FFd / 32), 256>>>(W2, FFd, Cc,  w216);
    // attention (bf16x3) -> fp16 split
    attn_kernel<<<dim3(Tt / 64, Hh, Bz), 128, AT_SMEM>>>(
        qkvh, qkvl,
        qkvh + (size_t)MM * Cc, qkvl + (size_t)MM * Cc,
        qkvh + (size_t)2 * MM * Cc, qkvl + (size_t)2 * MM * Cc,
        a_hi, a_lo);
    // out projection + bias + residual (fp16 2-term)
    tgemm16_kernel<EPI_RESID><<<gC, 256, GEMM16_SMEM>>>(MM, Cc, Cc, a_hi, a_lo, wp16,
                                                        bp, x, out, nullptr, nullptr);
    // LN2 -> fp16 split
    ln_kernel<1><<<MM, 256>>>(out, g2, be2, h2h, h2l);
    // MLP up + ReLU -> fp16 split
    tgemm16_kernel<EPI_RELUS><<<gF, 256, GEMM16_SMEM>>>(MM, FFd, Cc, h2h, h2l, w116,
                                                        b1, nullptr, nullptr, f_hi, f_lo);
    // MLP down + bias + residual
    tgemm16_kernel<EPI_RESID><<<gC, 256, GEMM16_SMEM>>>(MM, Cc, FFd, f_hi, f_lo, w216,
                                                        b2, out, out, nullptr, nullptr);
}

// round 7
// speedup vs baseline: 7.1732x; 1.1871x over previous
#include <cuda_runtime.h>
#include <cuda_fp16.h>
#include <math.h>
#include <stdint.h>

// Problem dims (fixed)
#define Bz 4
#define Tt 2048
#define Cc 1024
#define Hh 16
#define DHd 64
#define MM (Bz*Tt)      // 8192
#define FFd (4*Cc)      // 4096

typedef __half f16;

// ---------------- scratch ----------------
__device__ f16 g_h_hi[(size_t)MM * Cc];        // LN out (fp16 split) — reused LN1/LN2
__device__ f16 g_h_lo[(size_t)MM * Cc];
__device__ f16 g_q16h[(size_t)MM * Cc];        // [B,H,T,DH] q 2-term
__device__ f16 g_q16l[(size_t)MM * Cc];
__device__ f16 g_k16[(size_t)MM * Cc];         // k, v single fp16
__device__ f16 g_v16[(size_t)MM * Cc];
__device__ f16 g_attn_hi[(size_t)MM * Cc];
__device__ f16 g_attn_lo[(size_t)MM * Cc];
__device__ f16 g_ff_hi[(size_t)MM * FFd];
__device__ f16 g_ff_lo[(size_t)MM * FFd];
// transposed fp16 weights [N, K]
__device__ f16 g_Wqkv16[(size_t)3 * Cc * Cc];
__device__ f16 g_WpT16[(size_t)Cc * Cc];
__device__ f16 g_W1T16[(size_t)FFd * Cc];
__device__ f16 g_W2T16[(size_t)Cc * FFd];

// ---------------- helpers ----------------
__device__ __forceinline__ uint32_t smem_u32(const void* p) {
    uint32_t a;
    asm("{ .reg .u64 t; cvta.to.shared.u64 t, %1; cvt.u32.u64 %0, t; }"
        : "=r"(a) : "l"(p));
    return a;
}
__device__ __forceinline__ void cpasync16(uint32_t s, const void* g) {
    asm volatile("cp.async.cg.shared.global [%0], [%1], 16;" :: "r"(s), "l"(g));
}
__device__ __forceinline__ void cp_commit() {
    asm volatile("cp.async.commit_group;" ::: "memory");
}
__device__ __forceinline__ void ldsm4(uint32_t& r0, uint32_t& r1, uint32_t& r2,
                                      uint32_t& r3, uint32_t a) {
    asm volatile("ldmatrix.sync.aligned.m8n8.x4.shared.b16 {%0,%1,%2,%3}, [%4];"
                 : "=r"(r0), "=r"(r1), "=r"(r2), "=r"(r3) : "r"(a));
}
__device__ __forceinline__ void ldsm4t(uint32_t& r0, uint32_t& r1, uint32_t& r2,
                                       uint32_t& r3, uint32_t a) {
    asm volatile("ldmatrix.sync.aligned.m8n8.x4.trans.shared.b16 {%0,%1,%2,%3}, [%4];"
                 : "=r"(r0), "=r"(r1), "=r"(r2), "=r"(r3) : "r"(a));
}
__device__ __forceinline__ void mma16816h(float* c, const uint32_t* a,
                                          uint32_t b0, uint32_t b1) {
    asm volatile(
        "mma.sync.aligned.m16n8k16.row.col.f32.f16.f16.f32 "
        "{%0,%1,%2,%3}, {%4,%5,%6,%7}, {%8,%9}, {%0,%1,%2,%3};"
        : "+f"(c[0]), "+f"(c[1]), "+f"(c[2]), "+f"(c[3])
        : "r"(a[0]), "r"(a[1]), "r"(a[2]), "r"(a[3]), "r"(b0), "r"(b1));
}
__device__ __forceinline__ void hsplit(float v, f16& h, f16& l) {
    h = __float2half_rn(v);
    l = __float2half_rn(v - __half2float(h));
}
__device__ __forceinline__ void split2h(float a, float b, uint32_t& hi, uint32_t& lo) {
    f16 ah, al, bh, bl;
    hsplit(a, ah, al);
    hsplit(b, bh, bl);
    __half2 h2 = __halves2half2(ah, bh), l2 = __halves2half2(al, bl);
    hi = *reinterpret_cast<uint32_t*>(&h2);
    lo = *reinterpret_cast<uint32_t*>(&l2);
}
__device__ __forceinline__ uint32_t pack2h(float a, float b) {
    __half2 p = __floats2half2_rn(a, b);
    return *reinterpret_cast<uint32_t*>(&p);
}

// ---------------- LayerNorm -> fp16 hi/lo split ----------------
__global__ void __launch_bounds__(256) ln_kernel(
    const float* __restrict__ x, const float* __restrict__ g,
    const float* __restrict__ be, f16* __restrict__ ohi, f16* __restrict__ olo)
{
    int row = blockIdx.x;
    int t = threadIdx.x;
    float4 xv = reinterpret_cast<const float4*>(x + (size_t)row * Cc)[t];
    float s  = xv.x + xv.y + xv.z + xv.w;
    float s2 = xv.x*xv.x + xv.y*xv.y + xv.z*xv.z + xv.w*xv.w;
    #pragma unroll
    for (int off = 16; off > 0; off >>= 1) {
        s  += __shfl_xor_sync(0xffffffffu, s,  off);
        s2 += __shfl_xor_sync(0xffffffffu, s2, off);
    }
    __shared__ float ss[8], ss2[8];
    int w = t >> 5, lane = t & 31;
    if (lane == 0) { ss[w] = s; ss2[w] = s2; }
    __syncthreads();
    if (w == 0) {
        s  = (lane < 8) ? ss[lane]  : 0.f;
        s2 = (lane < 8) ? ss2[lane] : 0.f;
        #pragma unroll
        for (int off = 4; off > 0; off >>= 1) {
            s  += __shfl_xor_sync(0xffffffffu, s,  off);
            s2 += __shfl_xor_sync(0xffffffffu, s2, off);
        }
        if (lane == 0) { ss[0] = s; ss2[0] = s2; }
    }
    __syncthreads();
    float mu  = ss[0] * (1.f / Cc);
    float var = ss2[0] * (1.f / Cc) - mu * mu;
    float inv = rsqrtf(var + 1e-5f);
    float4 gv = reinterpret_cast<const float4*>(g)[t];
    float4 bv = reinterpret_cast<const float4*>(be)[t];
    float o0 = (xv.x - mu) * inv * gv.x + bv.x;
    float o1 = (xv.y - mu) * inv * gv.y + bv.y;
    float o2 = (xv.z - mu) * inv * gv.z + bv.z;
    float o3 = (xv.w - mu) * inv * gv.w + bv.w;
    uint32_t h01, l01, h23, l23;
    split2h(o0, o1, h01, l01);
    split2h(o2, o3, h23, l23);
    size_t base = (size_t)row * Cc + t * 4;
    uint32_t* ph = reinterpret_cast<uint32_t*>(ohi + base);
    uint32_t* pl = reinterpret_cast<uint32_t*>(olo + base);
    ph[0] = h01; ph[1] = h23;
    pl[0] = l01; pl[1] = l23;
}

// weight transpose -> single fp16:  W[K,N] -> WT [N,K]
__global__ void __launch_bounds__(256) wsplit16_kernel(
    const float* __restrict__ W, int K, int N, f16* __restrict__ T)
{
    __shared__ float ts[32][33];
    int k0 = blockIdx.y * 32, n0 = blockIdx.x * 32;
    int tx = threadIdx.x & 31, ty = threadIdx.x >> 5;
    #pragma unroll
    for (int r = 0; r < 32; r += 8)
        ts[ty + r][tx] = W[(size_t)(k0 + ty + r) * N + n0 + tx];
    __syncthreads();
    #pragma unroll
    for (int r = 0; r < 32; r += 8)
        T[(size_t)(n0 + ty + r) * K + k0 + tx] = __float2half_rn(ts[tx][ty + r]);
}

// ---------------- fp16 2-term GEMM (all layers), 3-stage ----------------
#define BM 128
#define BN 256
#define BK 64
#define LDSG 144
#define TSZ_A (128*LDSG)     // 18432
#define TSZ_B (256*LDSG)     // 36864
#define SA16_HI 0
#define SA16_LO TSZ_A
#define SB16    (2*TSZ_A)
#define STG16   (2*TSZ_A + TSZ_B)    // 73728
#define GEMM16_SMEM (3*STG16)        // 221184

#define EPI_QKV16 0
#define EPI_RESID 1
#define EPI_RELUS 2

template<int MODE>
__global__ void __launch_bounds__(256, 1)
tgemm16_kernel(int M, int N, int K,
               const f16* __restrict__ Ahi, const f16* __restrict__ Alo,
               const f16* __restrict__ B16,
               const float* __restrict__ bias, const float* __restrict__ res,
               float* __restrict__ out, f16* __restrict__ outh, f16* __restrict__ outl,
               f16* __restrict__ outk, f16* __restrict__ outv)
{
    extern __shared__ char smem[];
    uint32_t sb = smem_u32(smem);
    int tid = threadIdx.x;
    int w = tid >> 5, l = tid & 31;
    int wm = w >> 2, wn = w & 3;
    int m0 = blockIdx.y * BM, n0 = blockIdx.x * BN;

    float acc[4][8][4];
    #pragma unroll
    for (int i = 0; i < 4; i++)
        #pragma unroll
        for (int j = 0; j < 8; j++)
            #pragma unroll
            for (int r = 0; r < 4; r++) acc[i][j][r] = 0.f;

    int NT = K / BK;

    auto load_stage = [&](int t) {
        int kk = t * BK;
        uint32_t sbase = sb + (t % 3) * STG16;
        #pragma unroll
        for (int i = 0; i < 4; i++) {
            int c = tid + 256 * i;
            int row = c >> 3, col = c & 7;
            uint32_t so = row * LDSG + col * 16;
            size_t ga = (size_t)(m0 + row) * K + kk + col * 8;
            cpasync16(sbase + SA16_HI + so, Ahi + ga);
            cpasync16(sbase + SA16_LO + so, Alo + ga);
        }
        #pragma unroll
        for (int i = 0; i < 8; i++) {
            int c = tid + 256 * i;
            int row = c >> 3, col = c & 7;
            uint32_t so = row * LDSG + col * 16;
            size_t gb = (size_t)(n0 + row) * K + kk + col * 8;
            cpasync16(sbase + SB16 + so, B16 + gb);
        }
        cp_commit();
    };

    load_stage(0);
    load_stage(1);

    for (int t = 0; t < NT; t++) {
        if (t + 1 < NT) { asm volatile("cp.async.wait_group 1;" ::: "memory"); }
        else            { asm volatile("cp.async.wait_group 0;" ::: "memory"); }
        __syncthreads();
        if (t + 2 < NT) load_stage(t + 2);

        uint32_t sbase = sb + (t % 3) * STG16;
        #pragma unroll
        for (int hk = 0; hk < 4; hk++) {
            uint32_t ah[4][4], al[4][4];
            #pragma unroll
            for (int mi = 0; mi < 4; mi++) {
                uint32_t aaddr = sbase + SA16_HI
                               + (uint32_t)(wm * 64 + mi * 16 + (l & 15)) * LDSG
                               + hk * 32 + (l >> 4) * 16;
                ldsm4(ah[mi][0], ah[mi][1], ah[mi][2], ah[mi][3], aaddr);
                ldsm4(al[mi][0], al[mi][1], al[mi][2], al[mi][3], aaddr + TSZ_A);
            }
            #pragma unroll
            for (int p = 0; p < 4; p++) {
                uint32_t bh[4];
                uint32_t baddr = sbase + SB16
                               + (uint32_t)(wn * 64 + p * 16 + ((l >> 4) & 1) * 8 + (l & 7)) * LDSG
                               + hk * 32 + ((l >> 3) & 1) * 16;
                ldsm4(bh[0], bh[1], bh[2], bh[3], baddr);
                #pragma unroll
                for (int mi = 0; mi < 4; mi++) {
                    mma16816h(acc[mi][2*p],   ah[mi], bh[0], bh[1]);
                    mma16816h(acc[mi][2*p],   al[mi], bh[0], bh[1]);
                    mma16816h(acc[mi][2*p+1], ah[mi], bh[2], bh[3]);
                    mma16816h(acc[mi][2*p+1], al[mi], bh[2], bh[3]);
                }
            }
        }
    }

    // epilogue
    #pragma unroll
    for (int mi = 0; mi < 4; mi++) {
        #pragma unroll
        for (int ni = 0; ni < 8; ni++) {
            int r0 = m0 + wm * 64 + mi * 16 + (l >> 2);
            int c  = n0 + wn * 64 + ni * 8 + (l & 3) * 2;
            #pragma unroll
            for (int hfl = 0; hfl < 2; hfl++) {
                int r = r0 + hfl * 8;
                float v0 = acc[mi][ni][hfl * 2 + 0];
                float v1 = acc[mi][ni][hfl * 2 + 1];
                if (MODE == EPI_QKV16) {
                    int b = r / Tt, tt = r % Tt;
                    int sel = c >> 10;            // 0=q 1=k 2=v
                    int cc = c & 1023;
                    int hh = cc >> 6, d = cc & 63;
                    size_t idx = (((size_t)(b * Hh + hh) * Tt) + tt) * DHd + d;
                    if (sel == 0) {
                        uint32_t hi, lo;
                        split2h(v0, v1, hi, lo);
                        *reinterpret_cast<uint32_t*>(outh + idx) = hi;
                        *reinterpret_cast<uint32_t*>(outl + idx) = lo;
                    } else {
                        f16* dst = (sel == 1) ? outk : outv;
                        *reinterpret_cast<uint32_t*>(dst + idx) = pack2h(v0, v1);
                    }
                } else if (MODE == EPI_RESID) {
                    size_t idx = (size_t)r * N + c;
                    float2 bi = *reinterpret_cast<const float2*>(bias + c);
                    float2 rs = *reinterpret_cast<const float2*>(res + idx);
                    *reinterpret_cast<float2*>(out + idx) =
                        make_float2(v0 + bi.x + rs.x, v1 + bi.y + rs.y);
                } else {  // EPI_RELUS -> fp16 split
                    size_t idx = (size_t)r * N + c;
                    float2 bi = *reinterpret_cast<const float2*>(bias + c);
                    float a0 = fmaxf(v0 + bi.x, 0.f);
                    float a1 = fmaxf(v1 + bi.y, 0.f);
                    uint32_t hi, lo;
                    split2h(a0, a1, hi, lo);
                    *reinterpret_cast<uint32_t*>(outh + idx) = hi;
                    *reinterpret_cast<uint32_t*>(outl + idx) = lo;
                }
            }
        }
    }
}

// ---------------- Flash attention, fp16 (Q 2-term, K/V single) ----------------
#define ALD 144
#define AQH 0
#define AQL (64*ALD)              // 9216
#define AKV0 (2*64*ALD)           // 18432
#define KVSTG (2*64*ALD)          // 18432: K (9216) + V (9216)
#define AT_SMEM (AKV0 + 3*KVSTG)  // 73728

__global__ void __launch_bounds__(128, 1) attn_kernel(
    const f16* __restrict__ qh, const f16* __restrict__ ql,
    const f16* __restrict__ k16, const f16* __restrict__ v16,
    f16* __restrict__ ohi, f16* __restrict__ olo)
{
    extern __shared__ char smem[];
    uint32_t sb = smem_u32(smem);
    int qt = gridDim.x - 1 - blockIdx.x;   // LPT: heaviest tiles first
    int hd = blockIdx.y, b = blockIdx.z;
    int tid = threadIdx.x;
    int w = tid >> 5, l = tid & 31;
    size_t bh_row0 = (size_t)(b * Hh + hd) * Tt;
    int qrow0 = qt * 64 + w * 16;

    // load Q (hi/lo) into smem
    #pragma unroll
    for (int i = 0; i < 4; i++) {
        int c = tid + 128 * i;
        int row = c >> 3, col = c & 7;
        size_t g = (bh_row0 + (size_t)qt * 64 + row) * DHd + col * 8;
        uint32_t so = row * ALD + col * 16;
        *reinterpret_cast<float4*>(smem + AQH + so) =
            *reinterpret_cast<const float4*>(qh + g);
        *reinterpret_cast<float4*>(smem + AQL + so) =
            *reinterpret_cast<const float4*>(ql + g);
    }
    __syncthreads();
    uint32_t qfh[4][4], qfl[4][4];
    #pragma unroll
    for (int ks = 0; ks < 4; ks++) {
        uint32_t qaddr = sb + AQH + (uint32_t)(w * 16 + (l & 15)) * ALD
                       + ks * 32 + (l >> 4) * 16;
        ldsm4(qfh[ks][0], qfh[ks][1], qfh[ks][2], qfh[ks][3], qaddr);
        ldsm4(qfl[ks][0], qfl[ks][1], qfl[ks][2], qfl[ks][3], qaddr + AQL);
    }

    auto load_kv = [&](int j) {
        uint32_t sbase = sb + AKV0 + (j % 3) * KVSTG;
        #pragma unroll
        for (int i = 0; i < 4; i++) {
            int c = tid + 128 * i;
            int row = c >> 3, col = c & 7;
            size_t g = (bh_row0 + (size_t)j * 64 + row) * DHd + col * 8;
            uint32_t so = row * ALD + col * 16;
            cpasync16(sbase + 0    + so, k16 + g);
            cpasync16(sbase + 9216 + so, v16 + g);
        }
        cp_commit();
    };

    load_kv(0);
    if (qt >= 1) load_kv(1);

    float m0r = -INFINITY, m1r = -INFINITY, l0r = 0.f, l1r = 0.f;
    float oacc[8][4];
    #pragma unroll
    for (int i = 0; i < 8; i++)
        #pragma unroll
        for (int c = 0; c < 4; c++) oacc[i][c] = 0.f;

    const float scale = 0.125f;

    for (int j = 0; j <= qt; j++) {
        if (j < qt) { asm volatile("cp.async.wait_group 1;" ::: "memory"); }
        else        { asm volatile("cp.async.wait_group 0;" ::: "memory"); }
        __syncthreads();
        if (j + 2 <= qt) load_kv(j + 2);

        uint32_t sbase = sb + AKV0 + (j % 3) * KVSTG;

        // S = Q K^T
        float sacc[8][4];
        #pragma unroll
        for (int i = 0; i < 8; i++)
            #pragma unroll
            for (int c = 0; c < 4; c++) sacc[i][c] = 0.f;

        #pragma unroll
        for (int ks = 0; ks < 4; ks++) {
            #pragma unroll
            for (int p = 0; p < 4; p++) {
                uint32_t kf[4];
                uint32_t kaddr = sbase
                    + (uint32_t)(p * 16 + ((l >> 4) & 1) * 8 + (l & 7)) * ALD
                    + ks * 32 + ((l >> 3) & 1) * 16;
                ldsm4(kf[0], kf[1], kf[2], kf[3], kaddr);
                mma16816h(sacc[2*p],   qfh[ks], kf[0], kf[1]);
                mma16816h(sacc[2*p],   qfl[ks], kf[0], kf[1]);
                mma16816h(sacc[2*p+1], qfh[ks], kf[2], kf[3]);
                mma16816h(sacc[2*p+1], qfl[ks], kf[2], kf[3]);
            }
        }

        // online softmax
        int jbase = j * 64;
        bool diag = (j == qt);
        float mx0 = -INFINITY, mx1 = -INFINITY;
        #pragma unroll
        for (int ni = 0; ni < 8; ni++) {
            #pragma unroll
            for (int c = 0; c < 4; c++) {
                float s = sacc[ni][c] * scale;
                if (diag) {
                    int col = jbase + ni * 8 + (l & 3) * 2 + (c & 1);
                    int rg  = qrow0 + (l >> 2) + (c >> 1) * 8;
                    if (col > rg) s = -INFINITY;
                }
                sacc[ni][c] = s;
                if (c < 2) mx0 = fmaxf(mx0, s);
                else       mx1 = fmaxf(mx1, s);
            }
        }
        mx0 = fmaxf(mx0, __shfl_xor_sync(0xffffffffu, mx0, 1));
        mx0 = fmaxf(mx0, __shfl_xor_sync(0xffffffffu, mx0, 2));
        mx1 = fmaxf(mx1, __shfl_xor_sync(0xffffffffu, mx1, 1));
        mx1 = fmaxf(mx1, __shfl_xor_sync(0xffffffffu, mx1, 2));

        float mn0 = fmaxf(m0r, mx0), mn1 = fmaxf(m1r, mx1);
        float al0 = __expf(m0r - mn0), al1 = __expf(m1r - mn1);
        float ps0 = 0.f, ps1 = 0.f;
        #pragma unroll
        for (int ni = 0; ni < 8; ni++) {
            float p0 = __expf(sacc[ni][0] - mn0);
            float p1 = __expf(sacc[ni][1] - mn0);
            float p2 = __expf(sacc[ni][2] - mn1);
            float p3 = __expf(sacc[ni][3] - mn1);
            sacc[ni][0] = p0; sacc[ni][1] = p1;
            sacc[ni][2] = p2; sacc[ni][3] = p3;
            ps0 += p0 + p1; ps1 += p2 + p3;
        }
        ps0 += __shfl_xor_sync(0xffffffffu, ps0, 1);
        ps0 += __shfl_xor_sync(0xffffffffu, ps0, 2);
        ps1 += __shfl_xor_sync(0xffffffffu, ps1, 1);
        ps1 += __shfl_xor_sync(0xffffffffu, ps1, 2);
        l0r = l0r * al0 + ps0;
        l1r = l1r * al1 + ps1;
        m0r = mn0; m1r = mn1;

        #pragma unroll
        for (int ni = 0; ni < 8; ni++) {
            oacc[ni][0] *= al0; oacc[ni][1] *= al0;
            oacc[ni][2] *= al1; oacc[ni][3] *= al1;
        }

        // O += P V  (P fp16 2-term, V single)
        #pragma unroll
        for (int ks = 0; ks < 4; ks++) {
            uint32_t aH[4], aL[4];
            split2h(sacc[2*ks][0],   sacc[2*ks][1],   aH[0], aL[0]);
            split2h(sacc[2*ks][2],   sacc[2*ks][3],   aH[1], aL[1]);
            split2h(sacc[2*ks+1][0], sacc[2*ks+1][1], aH[2], aL[2]);
            split2h(sacc[2*ks+1][2], sacc[2*ks+1][3], aH[3], aL[3]);
            #pragma unroll
            for (int p = 0; p < 4; p++) {
                uint32_t vf[4];
                uint32_t vaddr = sbase + 9216
                    + (uint32_t)(ks * 16 + (l & 15)) * ALD
                    + p * 32 + (l >> 4) * 16;
                ldsm4t(vf[0], vf[1], vf[2], vf[3], vaddr);
                mma16816h(oacc[2*p],   aH, vf[0], vf[1]);
                mma16816h(oacc[2*p],   aL, vf[0], vf[1]);
                mma16816h(oacc[2*p+1], aH, vf[2], vf[3]);
                mma16816h(oacc[2*p+1], aL, vf[2], vf[3]);
            }
        }
        __syncthreads();
    }

    // write out [B,T,C] fp16 hi/lo (proj GEMM input)
    float inv0 = 1.f / l0r, inv1 = 1.f / l1r;
    #pragma unroll
    for (int ni = 0; ni < 8; ni++) {
        int col = hd * DHd + ni * 8 + (l & 3) * 2;
        #pragma unroll
        for (int hfl = 0; hfl < 2; hfl++) {
            int rg = qrow0 + (l >> 2) + hfl * 8;
            float inv = hfl ? inv1 : inv0;
            float v0 = oacc[ni][hfl * 2 + 0] * inv;
            float v1 = oacc[ni][hfl * 2 + 1] * inv;
            size_t idx = ((size_t)b * Tt + rg) * Cc + col;
            uint32_t hi, lo;
            split2h(v0, v1, hi, lo);
            *reinterpret_cast<uint32_t*>(ohi + idx) = hi;
            *reinterpret_cast<uint32_t*>(olo + idx) = lo;
        }
    }
}

// ---------------- launch ----------------
extern "C" void kernel_launch(void* const* d_in, const int* in_sizes, int n_in,
                              void* d_out, int out_size)
{
    const float* x   = (const float*)d_in[0];
    const float* Wq  = (const float*)d_in[1];
    const float* Wk  = (const float*)d_in[2];
    const float* Wv  = (const float*)d_in[3];
    const float* Wp  = (const float*)d_in[4];
    const float* bp  = (const float*)d_in[5];
    const float* W1  = (const float*)d_in[6];
    const float* b1  = (const float*)d_in[7];
    const float* W2  = (const float*)d_in[8];
    const float* b2  = (const float*)d_in[9];
    const float* g1  = (const float*)d_in[10];
    const float* be1 = (const float*)d_in[11];
    const float* g2  = (const float*)d_in[12];
    const float* be2 = (const float*)d_in[13];
    float* out = (float*)d_out;

    f16 *h_hi, *h_lo, *q16h, *q16l, *k16, *v16, *a_hi, *a_lo, *f_hi, *f_lo;
    f16 *wqkv16, *wp16, *w116, *w216;
    cudaGetSymbolAddress((void**)&h_hi,  g_h_hi);
    cudaGetSymbolAddress((void**)&h_lo,  g_h_lo);
    cudaGetSymbolAddress((void**)&q16h,  g_q16h);
    cudaGetSymbolAddress((void**)&q16l,  g_q16l);
    cudaGetSymbolAddress((void**)&k16,   g_k16);
    cudaGetSymbolAddress((void**)&v16,   g_v16);
    cudaGetSymbolAddress((void**)&a_hi,  g_attn_hi);
    cudaGetSymbolAddress((void**)&a_lo,  g_attn_lo);
    cudaGetSymbolAddress((void**)&f_hi,  g_ff_hi);
    cudaGetSymbolAddress((void**)&f_lo,  g_ff_lo);
    cudaGetSymbolAddress((void**)&wqkv16, g_Wqkv16);
    cudaGetSymbolAddress((void**)&wp16,  g_WpT16);
    cudaGetSymbolAddress((void**)&w116,  g_W1T16);
    cudaGetSymbolAddress((void**)&w216,  g_W2T16);

    cudaFuncSetAttribute(attn_kernel,
                         cudaFuncAttributeMaxDynamicSharedMemorySize, AT_SMEM);
    cudaFuncSetAttribute(tgemm16_kernel<EPI_QKV16>,
                         cudaFuncAttributeMaxDynamicSharedMemorySize, GEMM16_SMEM);
    cudaFuncSetAttribute(tgemm16_kernel<EPI_RESID>,
                         cudaFuncAttributeMaxDynamicSharedMemorySize, GEMM16_SMEM);
    cudaFuncSetAttribute(tgemm16_kernel<EPI_RELUS>,
                         cudaFuncAttributeMaxDynamicSharedMemorySize, GEMM16_SMEM);

    dim3 gQKV(3 * Cc / BN, MM / BM);  // (12, 64)
    dim3 gC(Cc / BN, MM / BM);        // (4, 64)
    dim3 gF(FFd / BN, MM / BM);       // (16, 64)

    // weight prep (launches 1-4)
    wsplit16_kernel<<<dim3(Cc / 32, Cc / 32), 256>>>(Wq, Cc, Cc, wqkv16);
    wsplit16_kernel<<<dim3(Cc / 32, Cc / 32), 256>>>(Wk, Cc, Cc, wqkv16 + Cc * Cc);
    wsplit16_kernel<<<dim3(Cc / 32, Cc / 32), 256>>>(Wv, Cc, Cc, wqkv16 + 2 * Cc * Cc);
    wsplit16_kernel<<<dim3(Cc / 32, Cc / 32), 256>>>(Wp, Cc, Cc, wp16);
    // 5. LN1 -> fp16 split
    ln_kernel<<<MM, 256>>>(x, g1, be1, h_hi, h_lo);
    // 6. fused QKV projection (ncu target)
    tgemm16_kernel<EPI_QKV16><<<gQKV, 256, GEMM16_SMEM>>>(
        MM, 3 * Cc, Cc, h_hi, h_lo, wqkv16,
        nullptr, nullptr, nullptr, q16h, q16l, k16, v16);
    // remaining weight splits
    wsplit16_kernel<<<dim3(FFd / 32, Cc / 32), 256>>>(W1, Cc,  FFd, w116);
    wsplit16_kernel<<<dim3(Cc / 32, FFd / 32), 256>>>(W2, FFd, Cc,  w216);
    // attention
    attn_kernel<<<dim3(Tt / 64, Hh, Bz), 128, AT_SMEM>>>(q16h, q16l, k16, v16,
                                                         a_hi, a_lo);
    // out projection + bias + residual
    tgemm16_kernel<EPI_RESID><<<gC, 256, GEMM16_SMEM>>>(
        MM, Cc, Cc, a_hi, a_lo, wp16, bp, x, out, nullptr, nullptr, nullptr, nullptr);
    // LN2 -> fp16 split (reuses h buffers)
    ln_kernel<<<MM, 256>>>(out, g2, be2, h_hi, h_lo);
    // MLP up + ReLU
    tgemm16_kernel<EPI_RELUS><<<gF, 256, GEMM16_SMEM>>>(
        MM, FFd, Cc, h_hi, h_lo, w116, b1, nullptr, nullptr, f_hi, f_lo, nullptr, nullptr);
    // MLP down + bias + residual
    tgemm16_kernel<EPI_RESID><<<gC, 256, GEMM16_SMEM>>>(
        MM, Cc, FFd, f_hi, f_lo, w216, b2, out, out, nullptr, nullptr, nullptr, nullptr);
}

// round 8
// speedup vs baseline: 11.4599x; 1.5976x over previous
#include <cuda_runtime.h>
#include <cuda_fp16.h>
#include <math.h>
#include <stdint.h>

// Problem dims (fixed)
#define Bz 4
#define Tt 2048
#define Cc 1024
#define Hh 16
#define DHd 64
#define MM (Bz*Tt)      // 8192
#define FFd (4*Cc)      // 4096

typedef __half f16;

// ---------------- scratch ----------------
__device__ f16 g_h16[(size_t)MM * Cc];         // LN out (single fp16)
__device__ f16 g_q16[(size_t)MM * Cc];         // [B,H,T,DH]
__device__ f16 g_k16[(size_t)MM * Cc];
__device__ f16 g_v16[(size_t)MM * Cc];
__device__ f16 g_attn16[(size_t)MM * Cc];
__device__ f16 g_ff16[(size_t)MM * FFd];
// transposed fp16 weights [N, K]
__device__ f16 g_Wqkv16[(size_t)3 * Cc * Cc];
__device__ f16 g_WpT16[(size_t)Cc * Cc];
__device__ f16 g_W1T16[(size_t)FFd * Cc];
__device__ f16 g_W2T16[(size_t)Cc * FFd];

// ---------------- helpers ----------------
__device__ __forceinline__ uint32_t smem_u32(const void* p) {
    uint32_t a;
    asm("{ .reg .u64 t; cvta.to.shared.u64 t, %1; cvt.u32.u64 %0, t; }"
        : "=r"(a) : "l"(p));
    return a;
}
__device__ __forceinline__ void cpasync16(uint32_t s, const void* g) {
    asm volatile("cp.async.cg.shared.global [%0], [%1], 16;" :: "r"(s), "l"(g));
}
__device__ __forceinline__ void cp_commit() {
    asm volatile("cp.async.commit_group;" ::: "memory");
}
__device__ __forceinline__ void ldsm4(uint32_t& r0, uint32_t& r1, uint32_t& r2,
                                      uint32_t& r3, uint32_t a) {
    asm volatile("ldmatrix.sync.aligned.m8n8.x4.shared.b16 {%0,%1,%2,%3}, [%4];"
                 : "=r"(r0), "=r"(r1), "=r"(r2), "=r"(r3) : "r"(a));
}
__device__ __forceinline__ void ldsm4t(uint32_t& r0, uint32_t& r1, uint32_t& r2,
                                       uint32_t& r3, uint32_t a) {
    asm volatile("ldmatrix.sync.aligned.m8n8.x4.trans.shared.b16 {%0,%1,%2,%3}, [%4];"
                 : "=r"(r0), "=r"(r1), "=r"(r2), "=r"(r3) : "r"(a));
}
__device__ __forceinline__ void mma16816h(float* c, const uint32_t* a,
                                          uint32_t b0, uint32_t b1) {
    asm volatile(
        "mma.sync.aligned.m16n8k16.row.col.f32.f16.f16.f32 "
        "{%0,%1,%2,%3}, {%4,%5,%6,%7}, {%8,%9}, {%0,%1,%2,%3};"
        : "+f"(c[0]), "+f"(c[1]), "+f"(c[2]), "+f"(c[3])
        : "r"(a[0]), "r"(a[1]), "r"(a[2]), "r"(a[3]), "r"(b0), "r"(b1));
}
__device__ __forceinline__ uint32_t pack2h(float a, float b) {
    __half2 p = __floats2half2_rn(a, b);
    return *reinterpret_cast<uint32_t*>(&p);
}

// ---------------- LayerNorm -> single fp16 ----------------
__global__ void __launch_bounds__(256) ln_kernel(
    const float* __restrict__ x, const float* __restrict__ g,
    const float* __restrict__ be, f16* __restrict__ o16)
{
    int row = blockIdx.x;
    int t = threadIdx.x;
    float4 xv = reinterpret_cast<const float4*>(x + (size_t)row * Cc)[t];
    float s  = xv.x + xv.y + xv.z + xv.w;
    float s2 = xv.x*xv.x + xv.y*xv.y + xv.z*xv.z + xv.w*xv.w;
    #pragma unroll
    for (int off = 16; off > 0; off >>= 1) {
        s  += __shfl_xor_sync(0xffffffffu, s,  off);
        s2 += __shfl_xor_sync(0xffffffffu, s2, off);
    }
    __shared__ float ss[8], ss2[8];
    int w = t >> 5, lane = t & 31;
    if (lane == 0) { ss[w] = s; ss2[w] = s2; }
    __syncthreads();
    if (w == 0) {
        s  = (lane < 8) ? ss[lane]  : 0.f;
        s2 = (lane < 8) ? ss2[lane] : 0.f;
        #pragma unroll
        for (int off = 4; off > 0; off >>= 1) {
            s  += __shfl_xor_sync(0xffffffffu, s,  off);
            s2 += __shfl_xor_sync(0xffffffffu, s2, off);
        }
        if (lane == 0) { ss[0] = s; ss2[0] = s2; }
    }
    __syncthreads();
    float mu  = ss[0] * (1.f / Cc);
    float var = ss2[0] * (1.f / Cc) - mu * mu;
    float inv = rsqrtf(var + 1e-5f);
    float4 gv = reinterpret_cast<const float4*>(g)[t];
    float4 bv = reinterpret_cast<const float4*>(be)[t];
    float o0 = (xv.x - mu) * inv * gv.x + bv.x;
    float o1 = (xv.y - mu) * inv * gv.y + bv.y;
    float o2 = (xv.z - mu) * inv * gv.z + bv.z;
    float o3 = (xv.w - mu) * inv * gv.w + bv.w;
    size_t base = (size_t)row * Cc + t * 4;
    uint32_t* po = reinterpret_cast<uint32_t*>(o16 + base);
    po[0] = pack2h(o0, o1);
    po[1] = pack2h(o2, o3);
}

// weight transpose -> single fp16:  W[K,N] -> WT [N,K]
__global__ void __launch_bounds__(256) wsplit16_kernel(
    const float* __restrict__ W, int K, int N, f16* __restrict__ T)
{
    __shared__ float ts[32][33];
    int k0 = blockIdx.y * 32, n0 = blockIdx.x * 32;
    int tx = threadIdx.x & 31, ty = threadIdx.x >> 5;
    #pragma unroll
    for (int r = 0; r < 32; r += 8)
        ts[ty + r][tx] = W[(size_t)(k0 + ty + r) * N + n0 + tx];
    __syncthreads();
    #pragma unroll
    for (int r = 0; r < 32; r += 8)
        T[(size_t)(n0 + ty + r) * K + k0 + tx] = __float2half_rn(ts[tx][ty + r]);
}

// ---------------- fp16 GEMM (single x single), 4-stage ----------------
#define BM 128
#define BN 256
#define BK 64
#define LDSG 144
#define TSZ_A (128*LDSG)     // 18432
#define TSZ_B (256*LDSG)     // 36864
#define SA16 0
#define SB16 TSZ_A
#define STG16 (TSZ_A + TSZ_B)        // 55296
#define GEMM16_SMEM (4*STG16)        // 221184

#define EPI_QKV16 0
#define EPI_RESID 1
#define EPI_RELUS 2

template<int MODE>
__global__ void __launch_bounds__(256, 1)
tgemm16_kernel(int M, int N, int K,
               const f16* __restrict__ A16, const f16* __restrict__ B16,
               const float* __restrict__ bias, const float* __restrict__ res,
               float* __restrict__ out, f16* __restrict__ out16,
               f16* __restrict__ outk, f16* __restrict__ outv)
{
    extern __shared__ char smem[];
    uint32_t sb = smem_u32(smem);
    int tid = threadIdx.x;
    int w = tid >> 5, l = tid & 31;
    int wm = w >> 2, wn = w & 3;
    int m0 = blockIdx.y * BM, n0 = blockIdx.x * BN;

    float acc[4][8][4];
    #pragma unroll
    for (int i = 0; i < 4; i++)
        #pragma unroll
        for (int j = 0; j < 8; j++)
            #pragma unroll
            for (int r = 0; r < 4; r++) acc[i][j][r] = 0.f;

    int NT = K / BK;

    auto load_stage = [&](int t) {
        int kk = t * BK;
        uint32_t sbase = sb + (t & 3) * STG16;
        #pragma unroll
        for (int i = 0; i < 4; i++) {
            int c = tid + 256 * i;
            int row = c >> 3, col = c & 7;
            uint32_t so = row * LDSG + col * 16;
            size_t ga = (size_t)(m0 + row) * K + kk + col * 8;
            cpasync16(sbase + SA16 + so, A16 + ga);
        }
        #pragma unroll
        for (int i = 0; i < 8; i++) {
            int c = tid + 256 * i;
            int row = c >> 3, col = c & 7;
            uint32_t so = row * LDSG + col * 16;
            size_t gb = (size_t)(n0 + row) * K + kk + col * 8;
            cpasync16(sbase + SB16 + so, B16 + gb);
        }
        cp_commit();
    };

    load_stage(0);
    load_stage(1);
    load_stage(2);

    for (int t = 0; t < NT; t++) {
        int pend = NT - t - 1; if (pend > 2) pend = 2;
        if (pend == 2)      { asm volatile("cp.async.wait_group 2;" ::: "memory"); }
        else if (pend == 1) { asm volatile("cp.async.wait_group 1;" ::: "memory"); }
        else                { asm volatile("cp.async.wait_group 0;" ::: "memory"); }
        __syncthreads();
        if (t + 3 < NT) load_stage(t + 3);

        uint32_t sbase = sb + (t & 3) * STG16;
        #pragma unroll
        for (int hk = 0; hk < 4; hk++) {
            uint32_t af[4][4];
            #pragma unroll
            for (int mi = 0; mi < 4; mi++) {
                uint32_t aaddr = sbase + SA16
                               + (uint32_t)(wm * 64 + mi * 16 + (l & 15)) * LDSG
                               + hk * 32 + (l >> 4) * 16;
                ldsm4(af[mi][0], af[mi][1], af[mi][2], af[mi][3], aaddr);
            }
            #pragma unroll
            for (int p = 0; p < 4; p++) {
                uint32_t bf[4];
                uint32_t baddr = sbase + SB16
                               + (uint32_t)(wn * 64 + p * 16 + ((l >> 4) & 1) * 8 + (l & 7)) * LDSG
                               + hk * 32 + ((l >> 3) & 1) * 16;
                ldsm4(bf[0], bf[1], bf[2], bf[3], baddr);
                #pragma unroll
                for (int mi = 0; mi < 4; mi++) {
                    mma16816h(acc[mi][2*p],   af[mi], bf[0], bf[1]);
                    mma16816h(acc[mi][2*p+1], af[mi], bf[2], bf[3]);
                }
            }
        }
    }

    // epilogue
    #pragma unroll
    for (int mi = 0; mi < 4; mi++) {
        #pragma unroll
        for (int ni = 0; ni < 8; ni++) {
            int r0 = m0 + wm * 64 + mi * 16 + (l >> 2);
            int c  = n0 + wn * 64 + ni * 8 + (l & 3) * 2;
            #pragma unroll
            for (int hfl = 0; hfl < 2; hfl++) {
                int r = r0 + hfl * 8;
                float v0 = acc[mi][ni][hfl * 2 + 0];
                float v1 = acc[mi][ni][hfl * 2 + 1];
                if (MODE == EPI_QKV16) {
                    int b = r / Tt, tt = r % Tt;
                    int sel = c >> 10;            // 0=q 1=k 2=v
                    int cc = c & 1023;
                    int hh = cc >> 6, d = cc & 63;
                    size_t idx = (((size_t)(b * Hh + hh) * Tt) + tt) * DHd + d;
                    f16* dst = (sel == 0) ? out16 : ((sel == 1) ? outk : outv);
                    *reinterpret_cast<uint32_t*>(dst + idx) = pack2h(v0, v1);
                } else if (MODE == EPI_RESID) {
                    size_t idx = (size_t)r * N + c;
                    float2 bi = *reinterpret_cast<const float2*>(bias + c);
                    float2 rs = *reinterpret_cast<const float2*>(res + idx);
                    *reinterpret_cast<float2*>(out + idx) =
                        make_float2(v0 + bi.x + rs.x, v1 + bi.y + rs.y);
                } else {  // EPI_RELUS -> single fp16
                    size_t idx = (size_t)r * N + c;
                    float2 bi = *reinterpret_cast<const float2*>(bias + c);
                    float a0 = fmaxf(v0 + bi.x, 0.f);
                    float a1 = fmaxf(v1 + bi.y, 0.f);
                    *reinterpret_cast<uint32_t*>(out16 + idx) = pack2h(a0, a1);
                }
            }
        }
    }
}

// ---------------- Flash attention, pure fp16 (fp32 accum) ----------------
#define ALD 144
#define AQ 0
#define AKV0 (64*ALD)             // 9216
#define KVSTG (2*64*ALD)          // 18432: K + V
#define AT_SMEM (AKV0 + 3*KVSTG)  // 64512

__global__ void __launch_bounds__(128, 1) attn_kernel(
    const f16* __restrict__ q16, const f16* __restrict__ k16,
    const f16* __restrict__ v16, f16* __restrict__ o16)
{
    extern __shared__ char smem[];
    uint32_t sb = smem_u32(smem);
    int qt = gridDim.x - 1 - blockIdx.x;   // LPT
    int hd = blockIdx.y, b = blockIdx.z;
    int tid = threadIdx.x;
    int w = tid >> 5, l = tid & 31;
    size_t bh_row0 = (size_t)(b * Hh + hd) * Tt;
    int qrow0 = qt * 64 + w * 16;

    // load Q into smem then registers
    #pragma unroll
    for (int i = 0; i < 4; i++) {
        int c = tid + 128 * i;
        int row = c >> 3, col = c & 7;
        size_t g = (bh_row0 + (size_t)qt * 64 + row) * DHd + col * 8;
        uint32_t so = row * ALD + col * 16;
        *reinterpret_cast<float4*>(smem + AQ + so) =
            *reinterpret_cast<const float4*>(q16 + g);
    }
    __syncthreads();
    uint32_t qf[4][4];
    #pragma unroll
    for (int ks = 0; ks < 4; ks++) {
        uint32_t qaddr = sb + AQ + (uint32_t)(w * 16 + (l & 15)) * ALD
                       + ks * 32 + (l >> 4) * 16;
        ldsm4(qf[ks][0], qf[ks][1], qf[ks][2], qf[ks][3], qaddr);
    }

    auto load_kv = [&](int j) {
        uint32_t sbase = sb + AKV0 + (j % 3) * KVSTG;
        #pragma unroll
        for (int i = 0; i < 4; i++) {
            int c = tid + 128 * i;
            int row = c >> 3, col = c & 7;
            size_t g = (bh_row0 + (size_t)j * 64 + row) * DHd + col * 8;
            uint32_t so = row * ALD + col * 16;
            cpasync16(sbase + 0    + so, k16 + g);
            cpasync16(sbase + 9216 + so, v16 + g);
        }
        cp_commit();
    };

    load_kv(0);
    if (qt >= 1) load_kv(1);

    float m0r = -INFINITY, m1r = -INFINITY, l0r = 0.f, l1r = 0.f;
    float oacc[8][4];
    #pragma unroll
    for (int i = 0; i < 8; i++)
        #pragma unroll
        for (int c = 0; c < 4; c++) oacc[i][c] = 0.f;

    const float scale = 0.125f;

    for (int j = 0; j <= qt; j++) {
        if (j < qt) { asm volatile("cp.async.wait_group 1;" ::: "memory"); }
        else        { asm volatile("cp.async.wait_group 0;" ::: "memory"); }
        __syncthreads();
        if (j + 2 <= qt) load_kv(j + 2);

        uint32_t sbase = sb + AKV0 + (j % 3) * KVSTG;

        // S = Q K^T
        float sacc[8][4];
        #pragma unroll
        for (int i = 0; i < 8; i++)
            #pragma unroll
            for (int c = 0; c < 4; c++) sacc[i][c] = 0.f;

        #pragma unroll
        for (int ks = 0; ks < 4; ks++) {
            #pragma unroll
            for (int p = 0; p < 4; p++) {
                uint32_t kf[4];
                uint32_t kaddr = sbase
                    + (uint32_t)(p * 16 + ((l >> 4) & 1) * 8 + (l & 7)) * ALD
                    + ks * 32 + ((l >> 3) & 1) * 16;
                ldsm4(kf[0], kf[1], kf[2], kf[3], kaddr);
                mma16816h(sacc[2*p],   qf[ks], kf[0], kf[1]);
                mma16816h(sacc[2*p+1], qf[ks], kf[2], kf[3]);
            }
        }

        // online softmax
        int jbase = j * 64;
        bool diag = (j == qt);
        float mx0 = -INFINITY, mx1 = -INFINITY;
        #pragma unroll
        for (int ni = 0; ni < 8; ni++) {
            #pragma unroll
            for (int c = 0; c < 4; c++) {
                float s = sacc[ni][c] * scale;
                if (diag) {
                    int col = jbase + ni * 8 + (l & 3) * 2 + (c & 1);
                    int rg  = qrow0 + (l >> 2) + (c >> 1) * 8;
                    if (col > rg) s = -INFINITY;
                }
                sacc[ni][c] = s;
                if (c < 2) mx0 = fmaxf(mx0, s);
                else       mx1 = fmaxf(mx1, s);
            }
        }
        mx0 = fmaxf(mx0, __shfl_xor_sync(0xffffffffu, mx0, 1));
        mx0 = fmaxf(mx0, __shfl_xor_sync(0xffffffffu, mx0, 2));
        mx1 = fmaxf(mx1, __shfl_xor_sync(0xffffffffu, mx1, 1));
        mx1 = fmaxf(mx1, __shfl_xor_sync(0xffffffffu, mx1, 2));

        float mn0 = fmaxf(m0r, mx0), mn1 = fmaxf(m1r, mx1);
        float al0 = __expf(m0r - mn0), al1 = __expf(m1r - mn1);
        float ps0 = 0.f, ps1 = 0.f;
        #pragma unroll
        for (int ni = 0; ni < 8; ni++) {
            float p0 = __expf(sacc[ni][0] - mn0);
            float p1 = __expf(sacc[ni][1] - mn0);
            float p2 = __expf(sacc[ni][2] - mn1);
            float p3 = __expf(sacc[ni][3] - mn1);
            sacc[ni][0] = p0; sacc[ni][1] = p1;
            sacc[ni][2] = p2; sacc[ni][3] = p3;
            ps0 += p0 + p1; ps1 += p2 + p3;
        }
        ps0 += __shfl_xor_sync(0xffffffffu, ps0, 1);
        ps0 += __shfl_xor_sync(0xffffffffu, ps0, 2);
        ps1 += __shfl_xor_sync(0xffffffffu, ps1, 1);
        ps1 += __shfl_xor_sync(0xffffffffu, ps1, 2);
        l0r = l0r * al0 + ps0;
        l1r = l1r * al1 + ps1;
        m0r = mn0; m1r = mn1;

        #pragma unroll
        for (int ni = 0; ni < 8; ni++) {
            oacc[ni][0] *= al0; oacc[ni][1] *= al0;
            oacc[ni][2] *= al1; oacc[ni][3] *= al1;
        }

        // O += P V
        #pragma unroll
        for (int ks = 0; ks < 4; ks++) {
            uint32_t aP[4];
            aP[0] = pack2h(sacc[2*ks][0],   sacc[2*ks][1]);
            aP[1] = pack2h(sacc[2*ks][2],   sacc[2*ks][3]);
            aP[2] = pack2h(sacc[2*ks+1][0], sacc[2*ks+1][1]);
            aP[3] = pack2h(sacc[2*ks+1][2], sacc[2*ks+1][3]);
            #pragma unroll
            for (int p = 0; p < 4; p++) {
                uint32_t vf[4];
                uint32_t vaddr = sbase + 9216
                    + (uint32_t)(ks * 16 + (l & 15)) * ALD
                    + p * 32 + (l >> 4) * 16;
                ldsm4t(vf[0], vf[1], vf[2], vf[3], vaddr);
                mma16816h(oacc[2*p],   aP, vf[0], vf[1]);
                mma16816h(oacc[2*p+1], aP, vf[2], vf[3]);
            }
        }
        __syncthreads();
    }

    // write out [B,T,C] single fp16
    float inv0 = 1.f / l0r, inv1 = 1.f / l1r;
    #pragma unroll
    for (int ni = 0; ni < 8; ni++) {
        int col = hd * DHd + ni * 8 + (l & 3) * 2;
        #pragma unroll
        for (int hfl = 0; hfl < 2; hfl++) {
            int rg = qrow0 + (l >> 2) + hfl * 8;
            float inv = hfl ? inv1 : inv0;
            float v0 = oacc[ni][hfl * 2 + 0] * inv;
            float v1 = oacc[ni][hfl * 2 + 1] * inv;
            size_t idx = ((size_t)b * Tt + rg) * Cc + col;
            *reinterpret_cast<uint32_t*>(o16 + idx) = pack2h(v0, v1);
        }
    }
}

// ---------------- launch ----------------
extern "C" void kernel_launch(void* const* d_in, const int* in_sizes, int n_in,
                              void* d_out, int out_size)
{
    const float* x   = (const float*)d_in[0];
    const float* Wq  = (const float*)d_in[1];
    const float* Wk  = (const float*)d_in[2];
    const float* Wv  = (const float*)d_in[3];
    const float* Wp  = (const float*)d_in[4];
    const float* bp  = (const float*)d_in[5];
    const float* W1  = (const float*)d_in[6];
    const float* b1  = (const float*)d_in[7];
    const float* W2  = (const float*)d_in[8];
    const float* b2  = (const float*)d_in[9];
    const float* g1  = (const float*)d_in[10];
    const float* be1 = (const float*)d_in[11];
    const float* g2  = (const float*)d_in[12];
    const float* be2 = (const float*)d_in[13];
    float* out = (float*)d_out;

    f16 *h16, *q16, *k16, *v16, *a16, *ff16;
    f16 *wqkv16, *wp16, *w116, *w216;
    cudaGetSymbolAddress((void**)&h16,  g_h16);
    cudaGetSymbolAddress((void**)&q16,  g_q16);
    cudaGetSymbolAddress((void**)&k16,  g_k16);
    cudaGetSymbolAddress((void**)&v16,  g_v16);
    cudaGetSymbolAddress((void**)&a16,  g_attn16);
    cudaGetSymbolAddress((void**)&ff16, g_ff16);
    cudaGetSymbolAddress((void**)&wqkv16, g_Wqkv16);
    cudaGetSymbolAddress((void**)&wp16, g_WpT16);
    cudaGetSymbolAddress((void**)&w116, g_W1T16);
    cudaGetSymbolAddress((void**)&w216, g_W2T16);

    cudaFuncSetAttribute(attn_kernel,
                         cudaFuncAttributeMaxDynamicSharedMemorySize, AT_SMEM);
    cudaFuncSetAttribute(tgemm16_kernel<EPI_QKV16>,
                         cudaFuncAttributeMaxDynamicSharedMemorySize, GEMM16_SMEM);
    cudaFuncSetAttribute(tgemm16_kernel<EPI_RESID>,
                         cudaFuncAttributeMaxDynamicSharedMemorySize, GEMM16_SMEM);
    cudaFuncSetAttribute(tgemm16_kernel<EPI_RELUS>,
                         cudaFuncAttributeMaxDynamicSharedMemorySize, GEMM16_SMEM);

    dim3 gQKV(3 * Cc / BN, MM / BM);  // (12, 64)
    dim3 gC(Cc / BN, MM / BM);        // (4, 64)
    dim3 gF(FFd / BN, MM / BM);       // (16, 64)

    // weight prep (launches 1-4)
    wsplit16_kernel<<<dim3(Cc / 32, Cc / 32), 256>>>(Wq, Cc, Cc, wqkv16);
    wsplit16_kernel<<<dim3(Cc / 32, Cc / 32), 256>>>(Wk, Cc, Cc, wqkv16 + Cc * Cc);
    wsplit16_kernel<<<dim3(Cc / 32, Cc / 32), 256>>>(Wv, Cc, Cc, wqkv16 + 2 * Cc * Cc);
    wsplit16_kernel<<<dim3(Cc / 32, Cc / 32), 256>>>(Wp, Cc, Cc, wp16);
    // 5. LN1
    ln_kernel<<<MM, 256>>>(x, g1, be1, h16);
    // 6. fused QKV projection (ncu target)
    tgemm16_kernel<EPI_QKV16><<<gQKV, 256, GEMM16_SMEM>>>(
        MM, 3 * Cc, Cc, h16, wqkv16, nullptr, nullptr, nullptr, q16, k16, v16);
    // remaining weight splits
    wsplit16_kernel<<<dim3(FFd / 32, Cc / 32), 256>>>(W1, Cc,  FFd, w116);
    wsplit16_kernel<<<dim3(Cc / 32, FFd / 32), 256>>>(W2, FFd, Cc,  w216);
    // attention
    attn_kernel<<<dim3(Tt / 64, Hh, Bz), 128, AT_SMEM>>>(q16, k16, v16, a16);
    // out projection + bias + residual
    tgemm16_kernel<EPI_RESID><<<gC, 256, GEMM16_SMEM>>>(
        MM, Cc, Cc, a16, wp16, bp, x, out, nullptr, nullptr, nullptr);
    // LN2
    ln_kernel<<<MM, 256>>>(out, g2, be2, h16);
    // MLP up + ReLU
    tgemm16_kernel<EPI_RELUS><<<gF, 256, GEMM16_SMEM>>>(
        MM, FFd, Cc, h16, w116, b1, nullptr, nullptr, ff16, nullptr, nullptr);
    // MLP down + bias + residual
    tgemm16_kernel<EPI_RESID><<<gC, 256, GEMM16_SMEM>>>(
        MM, Cc, FFd, ff16, w216, b2, out, out, nullptr, nullptr, nullptr);
}